// round 1
// baseline (speedup 1.0000x reference)
#include <cuda_runtime.h>
#include <math.h>

#define D_MODEL 1024
#define N_HEADS 16
#define HEAD_DIM 64
#define BATCH 2
#define SEQ 2048
#define M_TOT (BATCH * SEQ)   /* 4096 */

/* ---- scratch (allocation-free: __device__ globals) ---- */
__device__ float g_q[(size_t)M_TOT * D_MODEL];
__device__ float g_k[(size_t)M_TOT * D_MODEL];
__device__ float g_v[(size_t)M_TOT * D_MODEL];
__device__ float g_a[(size_t)M_TOT * D_MODEL];

/* ============================================================
 * SGEMM  C[M,N] = A[M,K] @ B[N,K]^T   (both row-major, NT form)
 * 64x64 tile, BK=16, 256 threads, 4x4 microtile.
 * ============================================================ */
#define GBM 64
#define GBN 64
#define GBK 16
#define GPAD 68   /* pad BM=64 rows to 68 to break STS bank conflicts */

__global__ void __launch_bounds__(256)
gemm_nt_kernel(const float* __restrict__ A, const float* __restrict__ B,
               float* __restrict__ C, int M, int N, int K)
{
    __shared__ float As[GBK][GPAD];
    __shared__ float Bs[GBK][GPAD];

    const int tid  = threadIdx.x;
    const int tx   = tid & 15;
    const int ty   = tid >> 4;
    const int lrow = tid >> 2;            /* 0..63 */
    const int lcol = (tid & 3) << 2;      /* 0,4,8,12 */

    const float* Ap = A + (size_t)(blockIdx.y * GBM + lrow) * K + lcol;
    const float* Bp = B + (size_t)(blockIdx.x * GBN + lrow) * K + lcol;

    float acc[4][4] = {};

    for (int k0 = 0; k0 < K; k0 += GBK) {
        float4 a4 = *(const float4*)(Ap + k0);
        float4 b4 = *(const float4*)(Bp + k0);
        As[lcol + 0][lrow] = a4.x; As[lcol + 1][lrow] = a4.y;
        As[lcol + 2][lrow] = a4.z; As[lcol + 3][lrow] = a4.w;
        Bs[lcol + 0][lrow] = b4.x; Bs[lcol + 1][lrow] = b4.y;
        Bs[lcol + 2][lrow] = b4.z; Bs[lcol + 3][lrow] = b4.w;
        __syncthreads();

        #pragma unroll
        for (int kk = 0; kk < GBK; kk++) {
            float a[4], b[4];
            #pragma unroll
            for (int i = 0; i < 4; i++) a[i] = As[kk][ty * 4 + i];
            #pragma unroll
            for (int j = 0; j < 4; j++) b[j] = Bs[kk][tx * 4 + j];
            #pragma unroll
            for (int i = 0; i < 4; i++)
                #pragma unroll
                for (int j = 0; j < 4; j++)
                    acc[i][j] = fmaf(a[i], b[j], acc[i][j]);
        }
        __syncthreads();
    }

    #pragma unroll
    for (int i = 0; i < 4; i++) {
        float4 o4 = make_float4(acc[i][0], acc[i][1], acc[i][2], acc[i][3]);
        *(float4*)(C + (size_t)(blockIdx.y * GBM + ty * 4 + i) * N
                     + blockIdx.x * GBN + tx * 4) = o4;
    }
}

/* ============================================================
 * RoPE (interleaved-pair variant matching the reference):
 *   out[j]    = x[2j]  *cos(t*f[(2j)%32])   - x[2j+1]*sin(t*f[(2j)%32])
 *   out[32+j] = x[2j]  *sin(t*f[(2j+1)%32]) + x[2j+1]*cos(t*f[(2j+1)%32])
 *   f[e] = 10000^(-e/32)
 * one warp per (b,s,h) row of 64 floats; row = buf + gw*64 since the
 * projection output layout is (b*s, h*64+d).
 * ============================================================ */
__global__ void __launch_bounds__(256)
rope_kernel(float* __restrict__ t)
{
    __shared__ float invf[32];
    const int tid = threadIdx.x;
    if (tid < 32) invf[tid] = (float)pow(10000.0, -(double)tid / 32.0);
    __syncthreads();

    const int gw   = (blockIdx.x * blockDim.x + tid) >> 5;  /* head-row idx */
    const int lane = tid & 31;
    const int bs   = gw >> 4;
    const int pos  = bs & (SEQ - 1);

    float* row = t + (size_t)gw * 64;
    float x0 = row[2 * lane];
    float x1 = row[2 * lane + 1];

    const int e1 = (2 * lane) & 31;
    const int e2 = (2 * lane + 1) & 31;
    float s1, c1, s2, c2;
    sincosf((float)pos * invf[e1], &s1, &c1);
    sincosf((float)pos * invf[e2], &s2, &c2);

    __syncwarp();   /* all lanes read before any lane overwrites the row */
    row[lane]      = x0 * c1 - x1 * s1;
    row[32 + lane] = x0 * s2 + x1 * c2;
}

/* ============================================================
 * Flash attention, causal. One block = 64 query rows of one (b,h).
 * K/V/P tiles in smem (pitch 65 -> conflict-free column reads),
 * online softmax with per-row (m,l) and 4-lane row reductions.
 * ============================================================ */
#define PITCH 65

__global__ void __launch_bounds__(256)
attn_kernel(const float* __restrict__ q, const float* __restrict__ k,
            const float* __restrict__ v, float* __restrict__ o)
{
    extern __shared__ float sm[];
    float* Qs   = sm;
    float* Ks   = Qs + 64 * PITCH;
    float* Vs   = Ks + 64 * PITCH;
    float* Ps   = Vs + 64 * PITCH;
    float* mrow = Ps + 64 * PITCH;
    float* lrow = mrow + 64;
    float* rsc  = lrow + 64;

    const int qb  = blockIdx.x;
    const int bh  = blockIdx.y;
    const int tid = threadIdx.x;
    const int tx  = tid & 15;
    const int ty  = tid >> 4;

    const size_t base = ((size_t)(bh >> 4) * SEQ) * D_MODEL + (bh & 15) * HEAD_DIM;

    /* load Q tile (64x64) */
    {
        const int row = tid >> 2;
        const int c0  = (tid & 3) << 4;
        const float* gp = q + base + (size_t)(qb * 64 + row) * D_MODEL + c0;
        #pragma unroll
        for (int f = 0; f < 4; f++) {
            float4 vv = *(const float4*)(gp + f * 4);
            float* d = Qs + row * PITCH + c0 + f * 4;
            d[0] = vv.x; d[1] = vv.y; d[2] = vv.z; d[3] = vv.w;
        }
    }
    if (tid < 64) { mrow[tid] = -1e30f; lrow[tid] = 0.0f; }

    float acc[4][4] = {};
    __syncthreads();

    for (int kb = 0; kb <= qb; kb++) {
        /* load K,V tiles */
        {
            const int row = tid >> 2;
            const int c0  = (tid & 3) << 4;
            const float* gk = k + base + (size_t)(kb * 64 + row) * D_MODEL + c0;
            const float* gv = v + base + (size_t)(kb * 64 + row) * D_MODEL + c0;
            #pragma unroll
            for (int f = 0; f < 4; f++) {
                float4 kv = *(const float4*)(gk + f * 4);
                float4 vv = *(const float4*)(gv + f * 4);
                float* dk = Ks + row * PITCH + c0 + f * 4;
                dk[0] = kv.x; dk[1] = kv.y; dk[2] = kv.z; dk[3] = kv.w;
                float* dv = Vs + row * PITCH + c0 + f * 4;
                dv[0] = vv.x; dv[1] = vv.y; dv[2] = vv.z; dv[3] = vv.w;
            }
        }
        __syncthreads();

        /* scores: S = Q @ K^T, 4x4 microtile */
        float s[4][4] = {};
        #pragma unroll 8
        for (int kk = 0; kk < 64; kk++) {
            float a[4], b[4];
            #pragma unroll
            for (int i = 0; i < 4; i++) a[i] = Qs[(ty * 4 + i) * PITCH + kk];
            #pragma unroll
            for (int j = 0; j < 4; j++) b[j] = Ks[(tx * 4 + j) * PITCH + kk];
            #pragma unroll
            for (int i = 0; i < 4; i++)
                #pragma unroll
                for (int j = 0; j < 4; j++)
                    s[i][j] = fmaf(a[i], b[j], s[i][j]);
        }

        const bool diag = (kb == qb);
        #pragma unroll
        for (int i = 0; i < 4; i++)
            #pragma unroll
            for (int j = 0; j < 4; j++) {
                float val = s[i][j] * 0.125f;  /* 1/sqrt(64) */
                if (diag && (tx * 4 + j > ty * 4 + i)) val = -1e30f;
                Ps[(ty * 4 + i) * PITCH + tx * 4 + j] = val;
            }
        __syncthreads();

        /* online softmax: row = tid/4, 4 lanes cooperate per row */
        {
            const int row = tid >> 2;
            const int qd  = tid & 3;
            const float mold = mrow[row];
            float mx = mold;
            for (int c = qd; c < 64; c += 4)
                mx = fmaxf(mx, Ps[row * PITCH + c]);
            mx = fmaxf(mx, __shfl_xor_sync(0xffffffffu, mx, 1));
            mx = fmaxf(mx, __shfl_xor_sync(0xffffffffu, mx, 2));
            float sum = 0.0f;
            for (int c = qd; c < 64; c += 4) {
                float p = __expf(Ps[row * PITCH + c] - mx);
                Ps[row * PITCH + c] = p;
                sum += p;
            }
            sum += __shfl_xor_sync(0xffffffffu, sum, 1);
            sum += __shfl_xor_sync(0xffffffffu, sum, 2);
            if (qd == 0) {
                float sc = __expf(mold - mx);
                rsc[row]  = sc;
                lrow[row] = lrow[row] * sc + sum;
                mrow[row] = mx;
            }
        }
        __syncthreads();

        /* O = O*rescale + P @ V */
        #pragma unroll
        for (int i = 0; i < 4; i++) {
            const float sc = rsc[ty * 4 + i];
            #pragma unroll
            for (int j = 0; j < 4; j++) acc[i][j] *= sc;
        }
        #pragma unroll 8
        for (int c = 0; c < 64; c++) {
            float p[4], vv[4];
            #pragma unroll
            for (int i = 0; i < 4; i++) p[i] = Ps[(ty * 4 + i) * PITCH + c];
            #pragma unroll
            for (int j = 0; j < 4; j++) vv[j] = Vs[c * PITCH + tx * 4 + j];
            #pragma unroll
            for (int i = 0; i < 4; i++)
                #pragma unroll
                for (int j = 0; j < 4; j++)
                    acc[i][j] = fmaf(p[i], vv[j], acc[i][j]);
        }
        __syncthreads();
    }

    /* epilogue: divide by l, store */
    #pragma unroll
    for (int i = 0; i < 4; i++) {
        const float inv = 1.0f / lrow[ty * 4 + i];
        float4 ov = make_float4(acc[i][0] * inv, acc[i][1] * inv,
                                acc[i][2] * inv, acc[i][3] * inv);
        *(float4*)(o + base + (size_t)(qb * 64 + ty * 4 + i) * D_MODEL + tx * 4) = ov;
    }
}

/* ============================================================ */
extern "C" void kernel_launch(void* const* d_in, const int* in_sizes, int n_in,
                              void* d_out, int out_size)
{
    const float* x  = (const float*)d_in[0];
    const float* Wq = (const float*)d_in[1];
    const float* Wk = (const float*)d_in[2];
    const float* Wv = (const float*)d_in[3];
    const float* Wo = (const float*)d_in[4];
    /* d_in[5] = attn_mask (tril) — causal mask is applied analytically */
    float* out = (float*)d_out;

    float *qp, *kp, *vp, *ap;
    cudaGetSymbolAddress((void**)&qp, g_q);
    cudaGetSymbolAddress((void**)&kp, g_k);
    cudaGetSymbolAddress((void**)&vp, g_v);
    cudaGetSymbolAddress((void**)&ap, g_a);

    const dim3 gg(D_MODEL / GBN, M_TOT / GBM);   /* (16, 64) */

    gemm_nt_kernel<<<gg, 256>>>(x, Wq, qp, M_TOT, D_MODEL, D_MODEL);
    gemm_nt_kernel<<<gg, 256>>>(x, Wk, kp, M_TOT, D_MODEL, D_MODEL);
    gemm_nt_kernel<<<gg, 256>>>(x, Wv, vp, M_TOT, D_MODEL, D_MODEL);

    /* 65536 head-rows, one warp each, 8 warps/block -> 8192 blocks */
    rope_kernel<<<8192, 256>>>(qp);
    rope_kernel<<<8192, 256>>>(kp);

    const size_t smem = (size_t)(4 * 64 * PITCH + 3 * 64) * sizeof(float); /* 67328 B */
    cudaFuncSetAttribute(attn_kernel,
                         cudaFuncAttributeMaxDynamicSharedMemorySize, (int)smem);
    attn_kernel<<<dim3(SEQ / 64, BATCH * N_HEADS), 256, smem>>>(qp, kp, vp, ap);

    gemm_nt_kernel<<<gg, 256>>>(ap, Wo, out, M_TOT, D_MODEL, D_MODEL);
}

// round 3
// speedup vs baseline: 1.3243x; 1.3243x over previous
#include <cuda_runtime.h>
#include <cuda_bf16.h>
#include <math.h>
#include <stdint.h>

#define D_MODEL 1024
#define N_HEADS 16
#define HEAD_DIM 64
#define BATCH 2
#define SEQ 2048
#define M_TOT (BATCH * SEQ)   /* 4096 */

/* ---- scratch (allocation-free: __device__ globals) ---- */
__device__ float g_q[(size_t)M_TOT * D_MODEL];
__device__ float g_k[(size_t)M_TOT * D_MODEL];
__device__ float g_v[(size_t)M_TOT * D_MODEL];
__device__ float g_a[(size_t)M_TOT * D_MODEL];

__device__ __forceinline__ uint32_t smem_to_u32(const void* p) {
    uint32_t a;
    asm("{ .reg .u64 t; cvta.to.shared.u64 t, %1; cvt.u32.u64 %0, t; }" : "=r"(a) : "l"(p));
    return a;
}

#define LDSM_X4(r0, r1, r2, r3, addr) \
    asm volatile("ldmatrix.sync.aligned.m8n8.x4.shared.b16 {%0,%1,%2,%3}, [%4];" \
                 : "=r"(r0), "=r"(r1), "=r"(r2), "=r"(r3) : "r"(addr))

#define MMA_BF16(c, a, b) \
    asm volatile("mma.sync.aligned.m16n8k16.row.col.f32.bf16.bf16.f32 " \
                 "{%0,%1,%2,%3},{%4,%5,%6,%7},{%8,%9},{%0,%1,%2,%3};" \
                 : "+f"((c)[0]), "+f"((c)[1]), "+f"((c)[2]), "+f"((c)[3]) \
                 : "r"((a)[0]), "r"((a)[1]), "r"((a)[2]), "r"((a)[3]), \
                   "r"((b)[0]), "r"((b)[1]))

__device__ __forceinline__ uint32_t pk_bf16x2(__nv_bfloat16 a, __nv_bfloat16 b) {
    return (uint32_t)__bfloat16_as_ushort(a) | ((uint32_t)__bfloat16_as_ushort(b) << 16);
}

/* split a float4 into hi/lo bf16x2-pair registers */
__device__ __forceinline__ void split4(float4 v, uint2& hi, uint2& lo) {
    __nv_bfloat16 h0 = __float2bfloat16_rn(v.x), h1 = __float2bfloat16_rn(v.y);
    __nv_bfloat16 h2 = __float2bfloat16_rn(v.z), h3 = __float2bfloat16_rn(v.w);
    __nv_bfloat16 l0 = __float2bfloat16_rn(v.x - __bfloat162float(h0));
    __nv_bfloat16 l1 = __float2bfloat16_rn(v.y - __bfloat162float(h1));
    __nv_bfloat16 l2 = __float2bfloat16_rn(v.z - __bfloat162float(h2));
    __nv_bfloat16 l3 = __float2bfloat16_rn(v.w - __bfloat162float(h3));
    hi = make_uint2(pk_bf16x2(h0, h1), pk_bf16x2(h2, h3));
    lo = make_uint2(pk_bf16x2(l0, l1), pk_bf16x2(l2, l3));
}

/* ============================================================
 * Split-bf16 mma.sync GEMM: C[M,N] = A[M,K] @ B[N,K]^T (fp32 io)
 * CTA 128x128, BK=32, 8 warps (2x4), warp tile 64x32.
 * Smem tiles: bf16, row pitch 80B (conflict-free ldmatrix).
 * C += Ah*Bh + Ah*Bl + Al*Bh  (fp32 accum; lo*lo dropped)
 * ============================================================ */
#define BM 128
#define BN 128
#define BK 32
#define SPITCH 80                     /* bytes per 32-bf16 row */
#define TBYTES (128 * SPITCH)         /* 10240 per tile */
#define STG (4 * TBYTES)              /* Ah, Al, Bh, Bl = 40960 */
#define GEMM_SMEM (2 * STG)           /* 81920 */

__global__ void __launch_bounds__(256, 1)
gemm_mma_kernel(const float* __restrict__ A, const float* __restrict__ B,
                float* __restrict__ C, int M, int N, int K)
{
    extern __shared__ char smem[];
    const uint32_t smem_u32 = smem_to_u32(smem);

    const int tid    = threadIdx.x;
    const int lane   = tid & 31;
    const int wid    = tid >> 5;
    const int warp_m = wid >> 2;       /* 0..1 */
    const int warp_n = wid & 3;        /* 0..3 */
    const int m0 = blockIdx.y * BM;
    const int n0 = blockIdx.x * BN;

    /* global load mapping: warp covers 4 full 128B chunk-rows */
    const int lrow = tid >> 3;         /* 0..31 */
    const int lcol = (tid & 7) * 4;    /* float col in chunk */
    const float* Ag = A + (size_t)(m0 + lrow) * K + lcol;
    const float* Bg = B + (size_t)(n0 + lrow) * K + lcol;
    const size_t rstride = (size_t)32 * K;
    const uint32_t sts_off = (uint32_t)lrow * SPITCH + (uint32_t)(tid & 7) * 8;

    /* ldmatrix base offsets (within a tile) */
    const uint32_t a_ld = (uint32_t)(warp_m * 64 + (lane & 15)) * SPITCH + (lane >> 4) * 16;
    const uint32_t b_ld = (uint32_t)(warp_n * 32 + (lane & 15)) * SPITCH + (lane >> 4) * 16;

    float acc[4][4][4] = {};
    float4 ar[4], br[4];

    const int nchunks = K / BK;        /* 32 */

    /* prefetch + stage 0 fill */
    #pragma unroll
    for (int r = 0; r < 4; r++) {
        ar[r] = *(const float4*)(Ag + r * rstride);
        br[r] = *(const float4*)(Bg + r * rstride);
    }
    {
        char* st = smem;
        #pragma unroll
        for (int r = 0; r < 4; r++) {
            uint2 hi, lo;
            split4(ar[r], hi, lo);
            *(uint2*)(st + 0 * TBYTES + sts_off + r * 32 * SPITCH) = hi;
            *(uint2*)(st + 1 * TBYTES + sts_off + r * 32 * SPITCH) = lo;
            split4(br[r], hi, lo);
            *(uint2*)(st + 2 * TBYTES + sts_off + r * 32 * SPITCH) = hi;
            *(uint2*)(st + 3 * TBYTES + sts_off + r * 32 * SPITCH) = lo;
        }
    }
    __syncthreads();

    for (int i = 0; i < nchunks; i++) {
        const int s = i & 1;

        if (i + 1 < nchunks) {
            const float* ap = Ag + (size_t)(i + 1) * BK;
            const float* bp = Bg + (size_t)(i + 1) * BK;
            #pragma unroll
            for (int r = 0; r < 4; r++) {
                ar[r] = *(const float4*)(ap + r * rstride);
                br[r] = *(const float4*)(bp + r * rstride);
            }
        }

        const uint32_t stb = smem_u32 + s * STG;
        #pragma unroll
        for (int ks = 0; ks < 2; ks++) {
            uint32_t ah[4][4], al[4][4], bh[4][2], bl[4][2];
            #pragma unroll
            for (int mt = 0; mt < 4; mt++) {
                LDSM_X4(ah[mt][0], ah[mt][1], ah[mt][2], ah[mt][3],
                        stb + 0 * TBYTES + a_ld + mt * 16 * SPITCH + ks * 32);
                LDSM_X4(al[mt][0], al[mt][1], al[mt][2], al[mt][3],
                        stb + 1 * TBYTES + a_ld + mt * 16 * SPITCH + ks * 32);
            }
            #pragma unroll
            for (int nb = 0; nb < 2; nb++) {
                uint32_t r0, r1, r2, r3;
                LDSM_X4(r0, r1, r2, r3,
                        stb + 2 * TBYTES + b_ld + nb * 16 * SPITCH + ks * 32);
                bh[nb * 2][0] = r0; bh[nb * 2][1] = r2;
                bh[nb * 2 + 1][0] = r1; bh[nb * 2 + 1][1] = r3;
                LDSM_X4(r0, r1, r2, r3,
                        stb + 3 * TBYTES + b_ld + nb * 16 * SPITCH + ks * 32);
                bl[nb * 2][0] = r0; bl[nb * 2][1] = r2;
                bl[nb * 2 + 1][0] = r1; bl[nb * 2 + 1][1] = r3;
            }
            #pragma unroll
            for (int mt = 0; mt < 4; mt++)
                #pragma unroll
                for (int nt = 0; nt < 4; nt++) {
                    MMA_BF16(acc[mt][nt], ah[mt], bh[nt]);
                    MMA_BF16(acc[mt][nt], ah[mt], bl[nt]);
                    MMA_BF16(acc[mt][nt], al[mt], bh[nt]);
                }
        }

        if (i + 1 < nchunks) {
            char* st = smem + (s ^ 1) * STG;
            #pragma unroll
            for (int r = 0; r < 4; r++) {
                uint2 hi, lo;
                split4(ar[r], hi, lo);
                *(uint2*)(st + 0 * TBYTES + sts_off + r * 32 * SPITCH) = hi;
                *(uint2*)(st + 1 * TBYTES + sts_off + r * 32 * SPITCH) = lo;
                split4(br[r], hi, lo);
                *(uint2*)(st + 2 * TBYTES + sts_off + r * 32 * SPITCH) = hi;
                *(uint2*)(st + 3 * TBYTES + sts_off + r * 32 * SPITCH) = lo;
            }
        }
        __syncthreads();
    }

    /* epilogue */
    #pragma unroll
    for (int mt = 0; mt < 4; mt++) {
        const int m = m0 + warp_m * 64 + mt * 16 + (lane >> 2);
        #pragma unroll
        for (int nt = 0; nt < 4; nt++) {
            const int n = n0 + warp_n * 32 + nt * 8 + (lane & 3) * 2;
            *(float2*)(C + (size_t)m * N + n) =
                make_float2(acc[mt][nt][0], acc[mt][nt][1]);
            *(float2*)(C + (size_t)(m + 8) * N + n) =
                make_float2(acc[mt][nt][2], acc[mt][nt][3]);
        }
    }
}

/* ============================================================
 * RoPE (matching reference):
 *   out[j]    = x[2j]*cos(t*f[(2j)%32])   - x[2j+1]*sin(t*f[(2j)%32])
 *   out[32+j] = x[2j]*sin(t*f[(2j+1)%32]) + x[2j+1]*cos(t*f[(2j+1)%32])
 * one warp per (b,s,h) row of 64 floats.
 * ============================================================ */
__global__ void __launch_bounds__(256)
rope_kernel(float* __restrict__ t)
{
    __shared__ float invf[32];
    const int tid = threadIdx.x;
    if (tid < 32) invf[tid] = (float)pow(10000.0, -(double)tid / 32.0);
    __syncthreads();

    const int gw   = (blockIdx.x * blockDim.x + tid) >> 5;
    const int lane = tid & 31;
    const int bs   = gw >> 4;
    const int pos  = bs & (SEQ - 1);

    float* row = t + (size_t)gw * 64;
    float x0 = row[2 * lane];
    float x1 = row[2 * lane + 1];

    const int e1 = (2 * lane) & 31;
    const int e2 = (2 * lane + 1) & 31;
    float s1, c1, s2, c2;
    sincosf((float)pos * invf[e1], &s1, &c1);
    sincosf((float)pos * invf[e2], &s2, &c2);

    __syncwarp();
    row[lane]      = x0 * c1 - x1 * s1;
    row[32 + lane] = x0 * s2 + x1 * c2;
}

/* ============================================================
 * Flash attention, causal (FFMA; next round: mma.sync port).
 * ============================================================ */
#define PITCH 65

__global__ void __launch_bounds__(256)
attn_kernel(const float* __restrict__ q, const float* __restrict__ k,
            const float* __restrict__ v, float* __restrict__ o)
{
    extern __shared__ float sm[];
    float* Qs   = sm;
    float* Ks   = Qs + 64 * PITCH;
    float* Vs   = Ks + 64 * PITCH;
    float* Ps   = Vs + 64 * PITCH;
    float* mrow = Ps + 64 * PITCH;
    float* lrow = mrow + 64;
    float* rsc  = lrow + 64;

    const int qb  = blockIdx.x;
    const int bh  = blockIdx.y;
    const int tid = threadIdx.x;
    const int tx  = tid & 15;
    const int ty  = tid >> 4;

    const size_t base = ((size_t)(bh >> 4) * SEQ) * D_MODEL + (bh & 15) * HEAD_DIM;

    {
        const int row = tid >> 2;
        const int c0  = (tid & 3) << 4;
        const float* gp = q + base + (size_t)(qb * 64 + row) * D_MODEL + c0;
        #pragma unroll
        for (int f = 0; f < 4; f++) {
            float4 vv = *(const float4*)(gp + f * 4);
            float* d = Qs + row * PITCH + c0 + f * 4;
            d[0] = vv.x; d[1] = vv.y; d[2] = vv.z; d[3] = vv.w;
        }
    }
    if (tid < 64) { mrow[tid] = -1e30f; lrow[tid] = 0.0f; }

    float acc[4][4] = {};
    __syncthreads();

    for (int kb = 0; kb <= qb; kb++) {
        {
            const int row = tid >> 2;
            const int c0  = (tid & 3) << 4;
            const float* gk = k + base + (size_t)(kb * 64 + row) * D_MODEL + c0;
            const float* gv = v + base + (size_t)(kb * 64 + row) * D_MODEL + c0;
            #pragma unroll
            for (int f = 0; f < 4; f++) {
                float4 kv = *(const float4*)(gk + f * 4);
                float4 vv = *(const float4*)(gv + f * 4);
                float* dk = Ks + row * PITCH + c0 + f * 4;
                dk[0] = kv.x; dk[1] = kv.y; dk[2] = kv.z; dk[3] = kv.w;
                float* dv = Vs + row * PITCH + c0 + f * 4;
                dv[0] = vv.x; dv[1] = vv.y; dv[2] = vv.z; dv[3] = vv.w;
            }
        }
        __syncthreads();

        float s[4][4] = {};
        #pragma unroll 8
        for (int kk = 0; kk < 64; kk++) {
            float a[4], b[4];
            #pragma unroll
            for (int i = 0; i < 4; i++) a[i] = Qs[(ty * 4 + i) * PITCH + kk];
            #pragma unroll
            for (int j = 0; j < 4; j++) b[j] = Ks[(tx * 4 + j) * PITCH + kk];
            #pragma unroll
            for (int i = 0; i < 4; i++)
                #pragma unroll
                for (int j = 0; j < 4; j++)
                    s[i][j] = fmaf(a[i], b[j], s[i][j]);
        }

        const bool diag = (kb == qb);
        #pragma unroll
        for (int i = 0; i < 4; i++)
            #pragma unroll
            for (int j = 0; j < 4; j++) {
                float val = s[i][j] * 0.125f;
                if (diag && (tx * 4 + j > ty * 4 + i)) val = -1e30f;
                Ps[(ty * 4 + i) * PITCH + tx * 4 + j] = val;
            }
        __syncthreads();

        {
            const int row = tid >> 2;
            const int qd  = tid & 3;
            const float mold = mrow[row];
            float mx = mold;
            for (int c = qd; c < 64; c += 4)
                mx = fmaxf(mx, Ps[row * PITCH + c]);
            mx = fmaxf(mx, __shfl_xor_sync(0xffffffffu, mx, 1));
            mx = fmaxf(mx, __shfl_xor_sync(0xffffffffu, mx, 2));
            float sum = 0.0f;
            for (int c = qd; c < 64; c += 4) {
                float p = __expf(Ps[row * PITCH + c] - mx);
                Ps[row * PITCH + c] = p;
                sum += p;
            }
            sum += __shfl_xor_sync(0xffffffffu, sum, 1);
            sum += __shfl_xor_sync(0xffffffffu, sum, 2);
            if (qd == 0) {
                float sc = __expf(mold - mx);
                rsc[row]  = sc;
                lrow[row] = lrow[row] * sc + sum;
                mrow[row] = mx;
            }
        }
        __syncthreads();

        #pragma unroll
        for (int i = 0; i < 4; i++) {
            const float sc = rsc[ty * 4 + i];
            #pragma unroll
            for (int j = 0; j < 4; j++) acc[i][j] *= sc;
        }
        #pragma unroll 8
        for (int c = 0; c < 64; c++) {
            float p[4], vv[4];
            #pragma unroll
            for (int i = 0; i < 4; i++) p[i] = Ps[(ty * 4 + i) * PITCH + c];
            #pragma unroll
            for (int j = 0; j < 4; j++) vv[j] = Vs[c * PITCH + tx * 4 + j];
            #pragma unroll
            for (int i = 0; i < 4; i++)
                #pragma unroll
                for (int j = 0; j < 4; j++)
                    acc[i][j] = fmaf(p[i], vv[j], acc[i][j]);
        }
        __syncthreads();
    }

    #pragma unroll
    for (int i = 0; i < 4; i++) {
        const float inv = 1.0f / lrow[ty * 4 + i];
        float4 ov = make_float4(acc[i][0] * inv, acc[i][1] * inv,
                                acc[i][2] * inv, acc[i][3] * inv);
        *(float4*)(o + base + (size_t)(qb * 64 + ty * 4 + i) * D_MODEL + tx * 4) = ov;
    }
}

/* ============================================================ */
extern "C" void kernel_launch(void* const* d_in, const int* in_sizes, int n_in,
                              void* d_out, int out_size)
{
    const float* x  = (const float*)d_in[0];
    const float* Wq = (const float*)d_in[1];
    const float* Wk = (const float*)d_in[2];
    const float* Wv = (const float*)d_in[3];
    const float* Wo = (const float*)d_in[4];
    float* out = (float*)d_out;

    float *qp, *kp, *vp, *ap;
    cudaGetSymbolAddress((void**)&qp, g_q);
    cudaGetSymbolAddress((void**)&kp, g_k);
    cudaGetSymbolAddress((void**)&vp, g_v);
    cudaGetSymbolAddress((void**)&ap, g_a);

    static bool attr_done = false;
    if (!attr_done) {
        cudaFuncSetAttribute(gemm_mma_kernel,
                             cudaFuncAttributeMaxDynamicSharedMemorySize, GEMM_SMEM);
        const size_t asmem = (size_t)(4 * 64 * PITCH + 3 * 64) * sizeof(float);
        cudaFuncSetAttribute(attn_kernel,
                             cudaFuncAttributeMaxDynamicSharedMemorySize, (int)asmem);
        attr_done = true;
    }

    const dim3 gg(D_MODEL / BN, M_TOT / BM);   /* (8, 32) */

    gemm_mma_kernel<<<gg, 256, GEMM_SMEM>>>(x, Wq, qp, M_TOT, D_MODEL, D_MODEL);
    gemm_mma_kernel<<<gg, 256, GEMM_SMEM>>>(x, Wk, kp, M_TOT, D_MODEL, D_MODEL);
    gemm_mma_kernel<<<gg, 256, GEMM_SMEM>>>(x, Wv, vp, M_TOT, D_MODEL, D_MODEL);

    rope_kernel<<<8192, 256>>>(qp);
    rope_kernel<<<8192, 256>>>(kp);

    const size_t asmem = (size_t)(4 * 64 * PITCH + 3 * 64) * sizeof(float);
    attn_kernel<<<dim3(SEQ / 64, BATCH * N_HEADS), 256, asmem>>>(qp, kp, vp, ap);

    gemm_mma_kernel<<<gg, 256, GEMM_SMEM>>>(ap, Wo, out, M_TOT, D_MODEL, D_MODEL);
}

// round 6
// speedup vs baseline: 2.2146x; 1.6723x over previous
#include <cuda_runtime.h>
#include <cuda_bf16.h>
#include <math.h>
#include <stdint.h>

#define D_MODEL 1024
#define N_HEADS 16
#define HEAD_DIM 64
#define BATCH 2
#define SEQ 2048
#define M_TOT (BATCH * SEQ)   /* 4096 */

/* ---- scratch (allocation-free: __device__ globals) ---- */
__device__ float g_q[(size_t)M_TOT * D_MODEL];
__device__ float g_k[(size_t)M_TOT * D_MODEL];
__device__ float g_v[(size_t)M_TOT * D_MODEL];
__device__ float g_a[(size_t)M_TOT * D_MODEL];
/* split-bf16 buffers */
__device__ __nv_bfloat16 g_qh[(size_t)M_TOT * D_MODEL];
__device__ __nv_bfloat16 g_ql[(size_t)M_TOT * D_MODEL];
__device__ __nv_bfloat16 g_kh[(size_t)M_TOT * D_MODEL];
__device__ __nv_bfloat16 g_kl[(size_t)M_TOT * D_MODEL];
__device__ __nv_bfloat16 g_vth[(size_t)M_TOT * D_MODEL];  /* [bh][d][S] */
__device__ __nv_bfloat16 g_vtl[(size_t)M_TOT * D_MODEL];

__device__ __forceinline__ uint32_t smem_to_u32(const void* p) {
    uint32_t a;
    asm("{ .reg .u64 t; cvta.to.shared.u64 t, %1; cvt.u32.u64 %0, t; }" : "=r"(a) : "l"(p));
    return a;
}

#define LDSM_X4(r0, r1, r2, r3, addr) \
    asm volatile("ldmatrix.sync.aligned.m8n8.x4.shared.b16 {%0,%1,%2,%3}, [%4];" \
                 : "=r"(r0), "=r"(r1), "=r"(r2), "=r"(r3) : "r"(addr))

#define MMA_BF16(c, a, b) \
    asm volatile("mma.sync.aligned.m16n8k16.row.col.f32.bf16.bf16.f32 " \
                 "{%0,%1,%2,%3},{%4,%5,%6,%7},{%8,%9},{%0,%1,%2,%3};" \
                 : "+f"((c)[0]), "+f"((c)[1]), "+f"((c)[2]), "+f"((c)[3]) \
                 : "r"((a)[0]), "r"((a)[1]), "r"((a)[2]), "r"((a)[3]), \
                   "r"((b)[0]), "r"((b)[1]))

__device__ __forceinline__ uint32_t pk_bf16x2(__nv_bfloat16 a, __nv_bfloat16 b) {
    return (uint32_t)__bfloat16_as_ushort(a) | ((uint32_t)__bfloat16_as_ushort(b) << 16);
}

__device__ __forceinline__ void split4(float4 v, uint2& hi, uint2& lo) {
    __nv_bfloat16 h0 = __float2bfloat16_rn(v.x), h1 = __float2bfloat16_rn(v.y);
    __nv_bfloat16 h2 = __float2bfloat16_rn(v.z), h3 = __float2bfloat16_rn(v.w);
    __nv_bfloat16 l0 = __float2bfloat16_rn(v.x - __bfloat162float(h0));
    __nv_bfloat16 l1 = __float2bfloat16_rn(v.y - __bfloat162float(h1));
    __nv_bfloat16 l2 = __float2bfloat16_rn(v.z - __bfloat162float(h2));
    __nv_bfloat16 l3 = __float2bfloat16_rn(v.w - __bfloat162float(h3));
    hi = make_uint2(pk_bf16x2(h0, h1), pk_bf16x2(h2, h3));
    lo = make_uint2(pk_bf16x2(l0, l1), pk_bf16x2(l2, l3));
}

/* ============================================================
 * Split-bf16 mma.sync GEMM (unchanged from round 3, proven).
 * ============================================================ */
#define BM 128
#define BN 128
#define BK 32
#define SPITCH 80
#define TBYTES (128 * SPITCH)
#define STG (4 * TBYTES)
#define GEMM_SMEM (2 * STG)

__global__ void __launch_bounds__(256, 1)
gemm_mma_kernel(const float* __restrict__ A, const float* __restrict__ B,
                float* __restrict__ C, int M, int N, int K)
{
    extern __shared__ char smem[];
    const uint32_t smem_u32 = smem_to_u32(smem);

    const int tid    = threadIdx.x;
    const int lane   = tid & 31;
    const int wid    = tid >> 5;
    const int warp_m = wid >> 2;
    const int warp_n = wid & 3;
    const int m0 = blockIdx.y * BM;
    const int n0 = blockIdx.x * BN;

    const int lrow = tid >> 3;
    const int lcol = (tid & 7) * 4;
    const float* Ag = A + (size_t)(m0 + lrow) * K + lcol;
    const float* Bg = B + (size_t)(n0 + lrow) * K + lcol;
    const size_t rstride = (size_t)32 * K;
    const uint32_t sts_off = (uint32_t)lrow * SPITCH + (uint32_t)(tid & 7) * 8;

    const uint32_t a_ld = (uint32_t)(warp_m * 64 + (lane & 15)) * SPITCH + (lane >> 4) * 16;
    const uint32_t b_ld = (uint32_t)(warp_n * 32 + (lane & 15)) * SPITCH + (lane >> 4) * 16;

    float acc[4][4][4] = {};
    float4 ar[4], br[4];

    const int nchunks = K / BK;

    #pragma unroll
    for (int r = 0; r < 4; r++) {
        ar[r] = *(const float4*)(Ag + r * rstride);
        br[r] = *(const float4*)(Bg + r * rstride);
    }
    {
        char* st = smem;
        #pragma unroll
        for (int r = 0; r < 4; r++) {
            uint2 hi, lo;
            split4(ar[r], hi, lo);
            *(uint2*)(st + 0 * TBYTES + sts_off + r * 32 * SPITCH) = hi;
            *(uint2*)(st + 1 * TBYTES + sts_off + r * 32 * SPITCH) = lo;
            split4(br[r], hi, lo);
            *(uint2*)(st + 2 * TBYTES + sts_off + r * 32 * SPITCH) = hi;
            *(uint2*)(st + 3 * TBYTES + sts_off + r * 32 * SPITCH) = lo;
        }
    }
    __syncthreads();

    for (int i = 0; i < nchunks; i++) {
        const int s = i & 1;

        if (i + 1 < nchunks) {
            const float* ap = Ag + (size_t)(i + 1) * BK;
            const float* bp = Bg + (size_t)(i + 1) * BK;
            #pragma unroll
            for (int r = 0; r < 4; r++) {
                ar[r] = *(const float4*)(ap + r * rstride);
                br[r] = *(const float4*)(bp + r * rstride);
            }
        }

        const uint32_t stb = smem_u32 + s * STG;
        #pragma unroll
        for (int ks = 0; ks < 2; ks++) {
            uint32_t ah[4][4], al[4][4], bh[4][2], bl[4][2];
            #pragma unroll
            for (int mt = 0; mt < 4; mt++) {
                LDSM_X4(ah[mt][0], ah[mt][1], ah[mt][2], ah[mt][3],
                        stb + 0 * TBYTES + a_ld + mt * 16 * SPITCH + ks * 32);
                LDSM_X4(al[mt][0], al[mt][1], al[mt][2], al[mt][3],
                        stb + 1 * TBYTES + a_ld + mt * 16 * SPITCH + ks * 32);
            }
            #pragma unroll
            for (int nb = 0; nb < 2; nb++) {
                uint32_t r0, r1, r2, r3;
                LDSM_X4(r0, r1, r2, r3,
                        stb + 2 * TBYTES + b_ld + nb * 16 * SPITCH + ks * 32);
                bh[nb * 2][0] = r0; bh[nb * 2][1] = r2;
                bh[nb * 2 + 1][0] = r1; bh[nb * 2 + 1][1] = r3;
                LDSM_X4(r0, r1, r2, r3,
                        stb + 3 * TBYTES + b_ld + nb * 16 * SPITCH + ks * 32);
                bl[nb * 2][0] = r0; bl[nb * 2][1] = r2;
                bl[nb * 2 + 1][0] = r1; bl[nb * 2 + 1][1] = r3;
            }
            #pragma unroll
            for (int mt = 0; mt < 4; mt++)
                #pragma unroll
                for (int nt = 0; nt < 4; nt++) {
                    MMA_BF16(acc[mt][nt], ah[mt], bh[nt]);
                    MMA_BF16(acc[mt][nt], ah[mt], bl[nt]);
                    MMA_BF16(acc[mt][nt], al[mt], bh[nt]);
                }
        }

        if (i + 1 < nchunks) {
            char* st = smem + (s ^ 1) * STG;
            #pragma unroll
            for (int r = 0; r < 4; r++) {
                uint2 hi, lo;
                split4(ar[r], hi, lo);
                *(uint2*)(st + 0 * TBYTES + sts_off + r * 32 * SPITCH) = hi;
                *(uint2*)(st + 1 * TBYTES + sts_off + r * 32 * SPITCH) = lo;
                split4(br[r], hi, lo);
                *(uint2*)(st + 2 * TBYTES + sts_off + r * 32 * SPITCH) = hi;
                *(uint2*)(st + 3 * TBYTES + sts_off + r * 32 * SPITCH) = lo;
            }
        }
        __syncthreads();
    }

    #pragma unroll
    for (int mt = 0; mt < 4; mt++) {
        const int m = m0 + warp_m * 64 + mt * 16 + (lane >> 2);
        #pragma unroll
        for (int nt = 0; nt < 4; nt++) {
            const int n = n0 + warp_n * 32 + nt * 8 + (lane & 3) * 2;
            *(float2*)(C + (size_t)m * N + n) =
                make_float2(acc[mt][nt][0], acc[mt][nt][1]);
            *(float2*)(C + (size_t)(m + 8) * N + n) =
                make_float2(acc[mt][nt][2], acc[mt][nt][3]);
        }
    }
}

/* ============================================================
 * RoPE + split to bf16 hi/lo (scale folded in).
 * ============================================================ */
__global__ void __launch_bounds__(256)
rope_split_kernel(const float* __restrict__ in,
                  __nv_bfloat16* __restrict__ oh, __nv_bfloat16* __restrict__ ol,
                  float scale)
{
    __shared__ float invf[32];
    const int tid = threadIdx.x;
    if (tid < 32) invf[tid] = (float)pow(10000.0, -(double)tid / 32.0);
    __syncthreads();

    const int gw   = (blockIdx.x * blockDim.x + tid) >> 5;
    const int lane = tid & 31;
    const int bs   = gw >> 4;
    const int pos  = bs & (SEQ - 1);

    const float* row = in + (size_t)gw * 64;
    float x0 = row[2 * lane];
    float x1 = row[2 * lane + 1];

    const int e1 = (2 * lane) & 31;
    const int e2 = (2 * lane + 1) & 31;
    float s1, c1, s2, c2;
    sincosf((float)pos * invf[e1], &s1, &c1);
    sincosf((float)pos * invf[e2], &s2, &c2);

    float y0 = (x0 * c1 - x1 * s1) * scale;
    float y1 = (x0 * s2 + x1 * c2) * scale;

    __nv_bfloat16 h0 = __float2bfloat16_rn(y0);
    __nv_bfloat16 l0 = __float2bfloat16_rn(y0 - __bfloat162float(h0));
    __nv_bfloat16 h1 = __float2bfloat16_rn(y1);
    __nv_bfloat16 l1 = __float2bfloat16_rn(y1 - __bfloat162float(h1));

    oh[(size_t)gw * 64 + lane]      = h0;
    ol[(size_t)gw * 64 + lane]      = l0;
    oh[(size_t)gw * 64 + 32 + lane] = h1;
    ol[(size_t)gw * 64 + 32 + lane] = l1;
}

/* ============================================================
 * V transpose + split: g_v (bs, h*64+d) -> vt [bh][d][S] bf16 hi/lo
 * ============================================================ */
__global__ void __launch_bounds__(256)
vtrans_kernel(const float* __restrict__ v,
              __nv_bfloat16* __restrict__ vth, __nv_bfloat16* __restrict__ vtl)
{
    __shared__ float t[64][65];
    const int sblk = blockIdx.x;
    const int bh   = blockIdx.y;
    const int tid  = threadIdx.x;

    {
        const int row = tid >> 2;
        const int c0  = (tid & 3) * 16;
        const size_t gaddr = ((size_t)(bh >> 4) * SEQ + sblk * 64 + row) * D_MODEL
                           + (bh & 15) * 64 + c0;
        #pragma unroll
        for (int f = 0; f < 4; f++) {
            float4 vv = *(const float4*)(v + gaddr + f * 4);
            t[row][c0 + f * 4 + 0] = vv.x; t[row][c0 + f * 4 + 1] = vv.y;
            t[row][c0 + f * 4 + 2] = vv.z; t[row][c0 + f * 4 + 3] = vv.w;
        }
    }
    __syncthreads();

    const int d  = tid >> 2;
    const int k0 = (tid & 3) * 16;
    __nv_bfloat16 hv[16], lv[16];
    #pragma unroll
    for (int kk = 0; kk < 16; kk++) {
        float x = t[k0 + kk][d];
        hv[kk] = __float2bfloat16_rn(x);
        lv[kk] = __float2bfloat16_rn(x - __bfloat162float(hv[kk]));
    }
    const size_t dst = ((size_t)bh * 64 + d) * SEQ + sblk * 64 + k0;
    *(uint4*)(vth + dst)     = *(uint4*)(hv);
    *(uint4*)(vth + dst + 8) = *(uint4*)(hv + 8);
    *(uint4*)(vtl + dst)     = *(uint4*)(lv);
    *(uint4*)(vtl + dst + 8) = *(uint4*)(lv + 8);
}

/* ============================================================
 * Flash attention, causal, split-bf16 mma.sync.
 * Block = 64 q-rows of one (b,h), 4 warps (16 rows each).
 * Q scaled by 1/8 upstream. P stays in registers.
 * Tiles: 64 rows x 128 data bytes, pitch AP=144 (conflict-free).
 * ============================================================ */
#define AP 144
#define ATILE (64 * AP)          /* 9216 */
#define ATTN_SMEM (6 * ATILE)    /* 55296 */

__global__ void __launch_bounds__(128)
attn_mma_kernel(const __nv_bfloat16* __restrict__ qh, const __nv_bfloat16* __restrict__ ql,
                const __nv_bfloat16* __restrict__ kh, const __nv_bfloat16* __restrict__ kl,
                const __nv_bfloat16* __restrict__ vth, const __nv_bfloat16* __restrict__ vtl,
                float* __restrict__ o)
{
    extern __shared__ __align__(16) char sm[];
    char* Qh = sm;             char* Ql = sm + ATILE;
    char* Kh = sm + 2 * ATILE; char* Kl = sm + 3 * ATILE;
    char* Vh = sm + 4 * ATILE; char* Vl = sm + 5 * ATILE;
    const uint32_t su = smem_to_u32(sm);

    const int qb   = gridDim.x - 1 - blockIdx.x;   /* heavy blocks first */
    const int bh   = blockIdx.y;
    const int tid  = threadIdx.x;
    const int lane = tid & 31;
    const int wid  = tid >> 5;

    const int b = bh >> 4, h = bh & 15;
    const size_t qkrow0 = ((size_t)b * SEQ) * D_MODEL + (size_t)h * 64;
    const size_t vtrow0 = ((size_t)bh * 64) * SEQ;

    /* tile loaders: 128 threads, 2 per 128B row */
    const int lrow = tid >> 1, lhalf = tid & 1;
    const uint32_t sts = (uint32_t)lrow * AP + lhalf * 64;

    /* load Q hi/lo */
    {
        const size_t g = qkrow0 + (size_t)(qb * 64 + lrow) * D_MODEL + lhalf * 32;
        const uint4* sh = (const uint4*)(qh + g);
        const uint4* sl = (const uint4*)(ql + g);
        uint4* dh = (uint4*)(Qh + sts);
        uint4* dl = (uint4*)(Ql + sts);
        #pragma unroll
        for (int f = 0; f < 4; f++) { dh[f] = sh[f]; dl[f] = sl[f]; }
    }

    const uint32_t a_ld  = su + (uint32_t)(wid * 16 + (lane & 15)) * AP + (lane >> 4) * 16;
    const uint32_t bk_ld = su + (uint32_t)(lane & 15) * AP + (lane >> 4) * 16;

    float acc[8][4] = {};
    float mo1 = -1e30f, mo2 = -1e30f, l1 = 0.0f, l2 = 0.0f;
    const int qrow = wid * 16 + (lane >> 2);

    for (int kb = 0; kb <= qb; kb++) {
        __syncthreads();
        /* load K hi/lo and Vt hi/lo tiles */
        {
            const size_t gk = qkrow0 + (size_t)(kb * 64 + lrow) * D_MODEL + lhalf * 32;
            const size_t gv = vtrow0 + (size_t)lrow * SEQ + kb * 64 + lhalf * 32;
            const uint4* skh = (const uint4*)(kh + gk);
            const uint4* skl = (const uint4*)(kl + gk);
            const uint4* svh = (const uint4*)(vth + gv);
            const uint4* svl = (const uint4*)(vtl + gv);
            uint4* dkh = (uint4*)(Kh + sts); uint4* dkl = (uint4*)(Kl + sts);
            uint4* dvh = (uint4*)(Vh + sts); uint4* dvl = (uint4*)(Vl + sts);
            #pragma unroll
            for (int f = 0; f < 4; f++) {
                dkh[f] = skh[f]; dkl[f] = skl[f];
                dvh[f] = svh[f]; dvl[f] = svl[f];
            }
        }
        __syncthreads();

        /* S = Q @ K^T (split, 3 terms) */
        float s[8][4] = {};
        #pragma unroll
        for (int ks = 0; ks < 4; ks++) {
            uint32_t ah[4], al[4];
            LDSM_X4(ah[0], ah[1], ah[2], ah[3], a_ld + ks * 32 + 0 * ATILE);
            LDSM_X4(al[0], al[1], al[2], al[3], a_ld + ks * 32 + 1 * ATILE);
            #pragma unroll
            for (int nb = 0; nb < 4; nb++) {
                uint32_t r0, r1, r2, r3, q0, q1, q2, q3;
                LDSM_X4(r0, r1, r2, r3, bk_ld + nb * 16 * AP + ks * 32 + 2 * ATILE);
                LDSM_X4(q0, q1, q2, q3, bk_ld + nb * 16 * AP + ks * 32 + 3 * ATILE);
                uint32_t be[2] = {r0, r2}, bo[2] = {r1, r3};
                uint32_t le[2] = {q0, q2}, lo_[2] = {q1, q3};
                MMA_BF16(s[2 * nb],     ah, be); MMA_BF16(s[2 * nb],     ah, le); MMA_BF16(s[2 * nb],     al, be);
                MMA_BF16(s[2 * nb + 1], ah, bo); MMA_BF16(s[2 * nb + 1], ah, lo_); MMA_BF16(s[2 * nb + 1], al, bo);
            }
        }

        /* causal mask on diagonal tile */
        if (kb == qb) {
            #pragma unroll
            for (int j = 0; j < 8; j++) {
                const int c = j * 8 + (lane & 3) * 2;
                if (c     > qrow)     s[j][0] = -1e30f;
                if (c + 1 > qrow)     s[j][1] = -1e30f;
                if (c     > qrow + 8) s[j][2] = -1e30f;
                if (c + 1 > qrow + 8) s[j][3] = -1e30f;
            }
        }

        /* online softmax (rows qrow, qrow+8) */
        float m1 = -1e30f, m2 = -1e30f;
        #pragma unroll
        for (int j = 0; j < 8; j++) {
            m1 = fmaxf(m1, fmaxf(s[j][0], s[j][1]));
            m2 = fmaxf(m2, fmaxf(s[j][2], s[j][3]));
        }
        m1 = fmaxf(m1, __shfl_xor_sync(0xffffffffu, m1, 1));
        m1 = fmaxf(m1, __shfl_xor_sync(0xffffffffu, m1, 2));
        m2 = fmaxf(m2, __shfl_xor_sync(0xffffffffu, m2, 1));
        m2 = fmaxf(m2, __shfl_xor_sync(0xffffffffu, m2, 2));
        const float mn1 = fmaxf(mo1, m1), mn2 = fmaxf(mo2, m2);
        const float sc1 = __expf(mo1 - mn1), sc2 = __expf(mo2 - mn2);
        float sum1 = 0.0f, sum2 = 0.0f;
        #pragma unroll
        for (int j = 0; j < 8; j++) {
            s[j][0] = __expf(s[j][0] - mn1); sum1 += s[j][0];
            s[j][1] = __expf(s[j][1] - mn1); sum1 += s[j][1];
            s[j][2] = __expf(s[j][2] - mn2); sum2 += s[j][2];
            s[j][3] = __expf(s[j][3] - mn2); sum2 += s[j][3];
        }
        sum1 += __shfl_xor_sync(0xffffffffu, sum1, 1);
        sum1 += __shfl_xor_sync(0xffffffffu, sum1, 2);
        sum2 += __shfl_xor_sync(0xffffffffu, sum2, 1);
        sum2 += __shfl_xor_sync(0xffffffffu, sum2, 2);
        l1 = l1 * sc1 + sum1; l2 = l2 * sc2 + sum2;
        mo1 = mn1; mo2 = mn2;
        #pragma unroll
        for (int j = 0; j < 8; j++) {
            acc[j][0] *= sc1; acc[j][1] *= sc1;
            acc[j][2] *= sc2; acc[j][3] *= sc2;
        }

        /* O += P @ V (P from registers, split) */
        #pragma unroll
        for (int ks = 0; ks < 4; ks++) {
            uint32_t ph[4], pl[4];
            #pragma unroll
            for (int t2 = 0; t2 < 2; t2++) {
                const int j = 2 * ks + t2;
                __nv_bfloat16 h0 = __float2bfloat16_rn(s[j][0]);
                __nv_bfloat16 h1 = __float2bfloat16_rn(s[j][1]);
                __nv_bfloat16 h2 = __float2bfloat16_rn(s[j][2]);
                __nv_bfloat16 h3 = __float2bfloat16_rn(s[j][3]);
                ph[2 * t2]     = pk_bf16x2(h0, h1);
                ph[2 * t2 + 1] = pk_bf16x2(h2, h3);
                pl[2 * t2]     = pk_bf16x2(
                    __float2bfloat16_rn(s[j][0] - __bfloat162float(h0)),
                    __float2bfloat16_rn(s[j][1] - __bfloat162float(h1)));
                pl[2 * t2 + 1] = pk_bf16x2(
                    __float2bfloat16_rn(s[j][2] - __bfloat162float(h2)),
                    __float2bfloat16_rn(s[j][3] - __bfloat162float(h3)));
            }
            #pragma unroll
            for (int nb = 0; nb < 4; nb++) {
                uint32_t r0, r1, r2, r3, q0, q1, q2, q3;
                LDSM_X4(r0, r1, r2, r3, bk_ld + nb * 16 * AP + ks * 32 + 4 * ATILE);
                LDSM_X4(q0, q1, q2, q3, bk_ld + nb * 16 * AP + ks * 32 + 5 * ATILE);
                uint32_t be[2] = {r0, r2}, bo[2] = {r1, r3};
                uint32_t le[2] = {q0, q2}, lo_[2] = {q1, q3};
                MMA_BF16(acc[2 * nb],     ph, be); MMA_BF16(acc[2 * nb],     ph, le); MMA_BF16(acc[2 * nb],     pl, be);
                MMA_BF16(acc[2 * nb + 1], ph, bo); MMA_BF16(acc[2 * nb + 1], ph, lo_); MMA_BF16(acc[2 * nb + 1], pl, bo);
            }
        }
    }

    /* epilogue */
    const float i1 = 1.0f / l1, i2 = 1.0f / l2;
    const size_t r1a = qkrow0 + (size_t)(qb * 64 + qrow) * D_MODEL;
    const size_t r2a = r1a + 8 * D_MODEL;
    #pragma unroll
    for (int j = 0; j < 8; j++) {
        const int c = j * 8 + (lane & 3) * 2;
        *(float2*)(o + r1a + c) = make_float2(acc[j][0] * i1, acc[j][1] * i1);
        *(float2*)(o + r2a + c) = make_float2(acc[j][2] * i2, acc[j][3] * i2);
    }
}

/* ============================================================ */
extern "C" void kernel_launch(void* const* d_in, const int* in_sizes, int n_in,
                              void* d_out, int out_size)
{
    const float* x  = (const float*)d_in[0];
    const float* Wq = (const float*)d_in[1];
    const float* Wk = (const float*)d_in[2];
    const float* Wv = (const float*)d_in[3];
    const float* Wo = (const float*)d_in[4];
    float* out = (float*)d_out;

    float *qp, *kp, *vp, *ap;
    __nv_bfloat16 *qhp, *qlp, *khp, *klp, *vthp, *vtlp;
    cudaGetSymbolAddress((void**)&qp, g_q);
    cudaGetSymbolAddress((void**)&kp, g_k);
    cudaGetSymbolAddress((void**)&vp, g_v);
    cudaGetSymbolAddress((void**)&ap, g_a);
    cudaGetSymbolAddress((void**)&qhp, g_qh);
    cudaGetSymbolAddress((void**)&qlp, g_ql);
    cudaGetSymbolAddress((void**)&khp, g_kh);
    cudaGetSymbolAddress((void**)&klp, g_kl);
    cudaGetSymbolAddress((void**)&vthp, g_vth);
    cudaGetSymbolAddress((void**)&vtlp, g_vtl);

    static bool attr_done = false;
    if (!attr_done) {
        cudaFuncSetAttribute(gemm_mma_kernel,
                             cudaFuncAttributeMaxDynamicSharedMemorySize, GEMM_SMEM);
        cudaFuncSetAttribute(attn_mma_kernel,
                             cudaFuncAttributeMaxDynamicSharedMemorySize, ATTN_SMEM);
        attr_done = true;
    }

    const dim3 gg(D_MODEL / BN, M_TOT / BM);

    gemm_mma_kernel<<<gg, 256, GEMM_SMEM>>>(x, Wq, qp, M_TOT, D_MODEL, D_MODEL);
    gemm_mma_kernel<<<gg, 256, GEMM_SMEM>>>(x, Wk, kp, M_TOT, D_MODEL, D_MODEL);
    gemm_mma_kernel<<<gg, 256, GEMM_SMEM>>>(x, Wv, vp, M_TOT, D_MODEL, D_MODEL);

    rope_split_kernel<<<8192, 256>>>(qp, qhp, qlp, 0.125f);  /* fold 1/sqrt(64) */
    rope_split_kernel<<<8192, 256>>>(kp, khp, klp, 1.0f);
    vtrans_kernel<<<dim3(SEQ / 64, BATCH * N_HEADS), 256>>>(vp, vthp, vtlp);

    attn_mma_kernel<<<dim3(SEQ / 64, BATCH * N_HEADS), 128, ATTN_SMEM>>>(
        qhp, qlp, khp, klp, vthp, vtlp, ap);

    gemm_mma_kernel<<<gg, 256, GEMM_SMEM>>>(ap, Wo, out, M_TOT, D_MODEL, D_MODEL);
}

// round 7
// speedup vs baseline: 2.4972x; 1.1276x over previous
#include <cuda_runtime.h>
#include <cuda_bf16.h>
#include <math.h>
#include <stdint.h>

#define D_MODEL 1024
#define N_HEADS 16
#define HEAD_DIM 64
#define BATCH 2
#define SEQ 2048
#define M_TOT (BATCH * SEQ)   /* 4096 */

/* ---- scratch (allocation-free: __device__ globals) ---- */
__device__ float g_q[(size_t)M_TOT * D_MODEL];
__device__ float g_k[(size_t)M_TOT * D_MODEL];
__device__ float g_v[(size_t)M_TOT * D_MODEL];
__device__ float g_a[(size_t)M_TOT * D_MODEL];
__device__ __nv_bfloat16 g_qh[(size_t)M_TOT * D_MODEL];
__device__ __nv_bfloat16 g_ql[(size_t)M_TOT * D_MODEL];
__device__ __nv_bfloat16 g_kh[(size_t)M_TOT * D_MODEL];
__device__ __nv_bfloat16 g_kl[(size_t)M_TOT * D_MODEL];
__device__ __nv_bfloat16 g_vth[(size_t)M_TOT * D_MODEL];  /* [bh][d][S] */
__device__ __nv_bfloat16 g_vtl[(size_t)M_TOT * D_MODEL];

__device__ __forceinline__ uint32_t smem_to_u32(const void* p) {
    uint32_t a;
    asm("{ .reg .u64 t; cvta.to.shared.u64 t, %1; cvt.u32.u64 %0, t; }" : "=r"(a) : "l"(p));
    return a;
}

#define LDSM_X4(r0, r1, r2, r3, addr) \
    asm volatile("ldmatrix.sync.aligned.m8n8.x4.shared.b16 {%0,%1,%2,%3}, [%4];" \
                 : "=r"(r0), "=r"(r1), "=r"(r2), "=r"(r3) : "r"(addr))

#define MMA_BF16(c, a, b) \
    asm volatile("mma.sync.aligned.m16n8k16.row.col.f32.bf16.bf16.f32 " \
                 "{%0,%1,%2,%3},{%4,%5,%6,%7},{%8,%9},{%0,%1,%2,%3};" \
                 : "+f"((c)[0]), "+f"((c)[1]), "+f"((c)[2]), "+f"((c)[3]) \
                 : "r"((a)[0]), "r"((a)[1]), "r"((a)[2]), "r"((a)[3]), \
                   "r"((b)[0]), "r"((b)[1]))

#define CP_ASYNC16(saddr, gptr) \
    asm volatile("cp.async.cg.shared.global [%0], [%1], 16;" \
                 :: "r"(saddr), "l"(gptr) : "memory")
#define CP_COMMIT() asm volatile("cp.async.commit_group;" ::: "memory")
#define CP_WAIT0()  asm volatile("cp.async.wait_group 0;" ::: "memory")
#define CP_WAIT1()  asm volatile("cp.async.wait_group 1;" ::: "memory")

__device__ __forceinline__ uint32_t pk_bf16x2(__nv_bfloat16 a, __nv_bfloat16 b) {
    return (uint32_t)__bfloat16_as_ushort(a) | ((uint32_t)__bfloat16_as_ushort(b) << 16);
}

__device__ __forceinline__ void split4(float4 v, uint2& hi, uint2& lo) {
    __nv_bfloat16 h0 = __float2bfloat16_rn(v.x), h1 = __float2bfloat16_rn(v.y);
    __nv_bfloat16 h2 = __float2bfloat16_rn(v.z), h3 = __float2bfloat16_rn(v.w);
    __nv_bfloat16 l0 = __float2bfloat16_rn(v.x - __bfloat162float(h0));
    __nv_bfloat16 l1 = __float2bfloat16_rn(v.y - __bfloat162float(h1));
    __nv_bfloat16 l2 = __float2bfloat16_rn(v.z - __bfloat162float(h2));
    __nv_bfloat16 l3 = __float2bfloat16_rn(v.w - __bfloat162float(h3));
    hi = make_uint2(pk_bf16x2(h0, h1), pk_bf16x2(h2, h3));
    lo = make_uint2(pk_bf16x2(l0, l1), pk_bf16x2(l2, l3));
}

/* ============================================================
 * Split-bf16 mma.sync GEMM (proven round-3 kernel, unchanged).
 * ============================================================ */
#define BM 128
#define BN 128
#define BK 32
#define SPITCH 80
#define TBYTES (128 * SPITCH)
#define STG (4 * TBYTES)
#define GEMM_SMEM (2 * STG)

__global__ void __launch_bounds__(256, 1)
gemm_mma_kernel(const float* __restrict__ A, const float* __restrict__ B,
                float* __restrict__ C, int M, int N, int K)
{
    extern __shared__ char smem[];
    const uint32_t smem_u32 = smem_to_u32(smem);

    const int tid    = threadIdx.x;
    const int lane   = tid & 31;
    const int wid    = tid >> 5;
    const int warp_m = wid >> 2;
    const int warp_n = wid & 3;
    const int m0 = blockIdx.y * BM;
    const int n0 = blockIdx.x * BN;

    const int lrow = tid >> 3;
    const float* Ag = A + (size_t)(m0 + lrow) * K + (tid & 7) * 4;
    const float* Bg = B + (size_t)(n0 + lrow) * K + (tid & 7) * 4;
    const size_t rstride = (size_t)32 * K;
    const uint32_t sts_off = (uint32_t)lrow * SPITCH + (uint32_t)(tid & 7) * 8;

    const uint32_t a_ld = (uint32_t)(warp_m * 64 + (lane & 15)) * SPITCH + (lane >> 4) * 16;
    const uint32_t b_ld = (uint32_t)(warp_n * 32 + (lane & 15)) * SPITCH + (lane >> 4) * 16;

    float acc[4][4][4] = {};
    float4 ar[4], br[4];

    const int nchunks = K / BK;

    #pragma unroll
    for (int r = 0; r < 4; r++) {
        ar[r] = *(const float4*)(Ag + r * rstride);
        br[r] = *(const float4*)(Bg + r * rstride);
    }
    {
        char* st = smem;
        #pragma unroll
        for (int r = 0; r < 4; r++) {
            uint2 hi, lo;
            split4(ar[r], hi, lo);
            *(uint2*)(st + 0 * TBYTES + sts_off + r * 32 * SPITCH) = hi;
            *(uint2*)(st + 1 * TBYTES + sts_off + r * 32 * SPITCH) = lo;
            split4(br[r], hi, lo);
            *(uint2*)(st + 2 * TBYTES + sts_off + r * 32 * SPITCH) = hi;
            *(uint2*)(st + 3 * TBYTES + sts_off + r * 32 * SPITCH) = lo;
        }
    }
    __syncthreads();

    for (int i = 0; i < nchunks; i++) {
        const int s = i & 1;

        if (i + 1 < nchunks) {
            const float* ap = Ag + (size_t)(i + 1) * BK;
            const float* bp = Bg + (size_t)(i + 1) * BK;
            #pragma unroll
            for (int r = 0; r < 4; r++) {
                ar[r] = *(const float4*)(ap + r * rstride);
                br[r] = *(const float4*)(bp + r * rstride);
            }
        }

        const uint32_t stb = smem_u32 + s * STG;
        #pragma unroll
        for (int ks = 0; ks < 2; ks++) {
            uint32_t ah[4][4], al[4][4], bh[4][2], bl[4][2];
            #pragma unroll
            for (int mt = 0; mt < 4; mt++) {
                LDSM_X4(ah[mt][0], ah[mt][1], ah[mt][2], ah[mt][3],
                        stb + 0 * TBYTES + a_ld + mt * 16 * SPITCH + ks * 32);
                LDSM_X4(al[mt][0], al[mt][1], al[mt][2], al[mt][3],
                        stb + 1 * TBYTES + a_ld + mt * 16 * SPITCH + ks * 32);
            }
            #pragma unroll
            for (int nb = 0; nb < 2; nb++) {
                uint32_t r0, r1, r2, r3;
                LDSM_X4(r0, r1, r2, r3,
                        stb + 2 * TBYTES + b_ld + nb * 16 * SPITCH + ks * 32);
                bh[nb * 2][0] = r0; bh[nb * 2][1] = r2;
                bh[nb * 2 + 1][0] = r1; bh[nb * 2 + 1][1] = r3;
                LDSM_X4(r0, r1, r2, r3,
                        stb + 3 * TBYTES + b_ld + nb * 16 * SPITCH + ks * 32);
                bl[nb * 2][0] = r0; bl[nb * 2][1] = r2;
                bl[nb * 2 + 1][0] = r1; bl[nb * 2 + 1][1] = r3;
            }
            #pragma unroll
            for (int mt = 0; mt < 4; mt++)
                #pragma unroll
                for (int nt = 0; nt < 4; nt++) {
                    MMA_BF16(acc[mt][nt], ah[mt], bh[nt]);
                    MMA_BF16(acc[mt][nt], ah[mt], bl[nt]);
                    MMA_BF16(acc[mt][nt], al[mt], bh[nt]);
                }
        }

        if (i + 1 < nchunks) {
            char* st = smem + (s ^ 1) * STG;
            #pragma unroll
            for (int r = 0; r < 4; r++) {
                uint2 hi, lo;
                split4(ar[r], hi, lo);
                *(uint2*)(st + 0 * TBYTES + sts_off + r * 32 * SPITCH) = hi;
                *(uint2*)(st + 1 * TBYTES + sts_off + r * 32 * SPITCH) = lo;
                split4(br[r], hi, lo);
                *(uint2*)(st + 2 * TBYTES + sts_off + r * 32 * SPITCH) = hi;
                *(uint2*)(st + 3 * TBYTES + sts_off + r * 32 * SPITCH) = lo;
            }
        }
        __syncthreads();
    }

    #pragma unroll
    for (int mt = 0; mt < 4; mt++) {
        const int m = m0 + warp_m * 64 + mt * 16 + (lane >> 2);
        #pragma unroll
        for (int nt = 0; nt < 4; nt++) {
            const int n = n0 + warp_n * 32 + nt * 8 + (lane & 3) * 2;
            *(float2*)(C + (size_t)m * N + n) =
                make_float2(acc[mt][nt][0], acc[mt][nt][1]);
            *(float2*)(C + (size_t)(m + 8) * N + n) =
                make_float2(acc[mt][nt][2], acc[mt][nt][3]);
        }
    }
}

/* ============================================================
 * Fused RoPE for Q and K: one warp per (b,s) position; sincos
 * computed once, reused across all 16 heads and both tensors.
 * ============================================================ */
__global__ void __launch_bounds__(256)
rope2_kernel(const float* __restrict__ q, const float* __restrict__ k,
             __nv_bfloat16* __restrict__ qh, __nv_bfloat16* __restrict__ ql,
             __nv_bfloat16* __restrict__ kh, __nv_bfloat16* __restrict__ kl)
{
    __shared__ float invf[32];
    const int tid = threadIdx.x;
    if (tid < 32) invf[tid] = (float)pow(10000.0, -(double)tid / 32.0);
    __syncthreads();

    const int bs   = blockIdx.x * 8 + (tid >> 5);   /* 0..4095 */
    const int lane = tid & 31;
    const int pos  = bs & (SEQ - 1);

    float s1, c1, s2, c2;
    sincosf((float)pos * invf[(2 * lane) & 31],     &s1, &c1);
    sincosf((float)pos * invf[(2 * lane + 1) & 31], &s2, &c2);

    const size_t base = (size_t)bs * D_MODEL;
    #pragma unroll
    for (int h = 0; h < N_HEADS; h++) {
        const size_t ro = base + h * 64;
        {
            float x0 = q[ro + 2 * lane], x1 = q[ro + 2 * lane + 1];
            float y0 = (x0 * c1 - x1 * s1) * 0.125f;
            float y1 = (x0 * s2 + x1 * c2) * 0.125f;
            __nv_bfloat16 h0 = __float2bfloat16_rn(y0);
            __nv_bfloat16 h1 = __float2bfloat16_rn(y1);
            qh[ro + lane]      = h0;
            ql[ro + lane]      = __float2bfloat16_rn(y0 - __bfloat162float(h0));
            qh[ro + 32 + lane] = h1;
            ql[ro + 32 + lane] = __float2bfloat16_rn(y1 - __bfloat162float(h1));
        }
        {
            float x0 = k[ro + 2 * lane], x1 = k[ro + 2 * lane + 1];
            float y0 = x0 * c1 - x1 * s1;
            float y1 = x0 * s2 + x1 * c2;
            __nv_bfloat16 h0 = __float2bfloat16_rn(y0);
            __nv_bfloat16 h1 = __float2bfloat16_rn(y1);
            kh[ro + lane]      = h0;
            kl[ro + lane]      = __float2bfloat16_rn(y0 - __bfloat162float(h0));
            kh[ro + 32 + lane] = h1;
            kl[ro + 32 + lane] = __float2bfloat16_rn(y1 - __bfloat162float(h1));
        }
    }
}

/* ============================================================
 * V transpose + split (unchanged).
 * ============================================================ */
__global__ void __launch_bounds__(256)
vtrans_kernel(const float* __restrict__ v,
              __nv_bfloat16* __restrict__ vth, __nv_bfloat16* __restrict__ vtl)
{
    __shared__ float t[64][65];
    const int sblk = blockIdx.x;
    const int bh   = blockIdx.y;
    const int tid  = threadIdx.x;

    {
        const int row = tid >> 2;
        const int c0  = (tid & 3) * 16;
        const size_t gaddr = ((size_t)(bh >> 4) * SEQ + sblk * 64 + row) * D_MODEL
                           + (bh & 15) * 64 + c0;
        #pragma unroll
        for (int f = 0; f < 4; f++) {
            float4 vv = *(const float4*)(v + gaddr + f * 4);
            t[row][c0 + f * 4 + 0] = vv.x; t[row][c0 + f * 4 + 1] = vv.y;
            t[row][c0 + f * 4 + 2] = vv.z; t[row][c0 + f * 4 + 3] = vv.w;
        }
    }
    __syncthreads();

    const int d  = tid >> 2;
    const int k0 = (tid & 3) * 16;
    __nv_bfloat16 hv[16], lv[16];
    #pragma unroll
    for (int kk = 0; kk < 16; kk++) {
        float x = t[k0 + kk][d];
        hv[kk] = __float2bfloat16_rn(x);
        lv[kk] = __float2bfloat16_rn(x - __bfloat162float(hv[kk]));
    }
    const size_t dst = ((size_t)bh * 64 + d) * SEQ + sblk * 64 + k0;
    *(uint4*)(vth + dst)     = *(uint4*)(hv);
    *(uint4*)(vth + dst + 8) = *(uint4*)(hv + 8);
    *(uint4*)(vtl + dst)     = *(uint4*)(lv);
    *(uint4*)(vtl + dst + 8) = *(uint4*)(lv + 8);
}

/* ============================================================
 * Flash attention, causal, split-bf16 mma.sync, cp.async pipeline.
 * Block = 128 q-rows of one (b,h), 8 warps (16 rows each).
 * K/V tiles (64 keys) double-buffered via cp.async.
 * ============================================================ */
#define AQP 144
#define AQTILE (128 * AQP)            /* 18432 */
#define AKTILE (64 * AQP)             /* 9216  */
#define ASTAGE (4 * AKTILE)           /* 36864 */
#define ATTN_SMEM (2 * AQTILE + 2 * ASTAGE)  /* 110592 */

__global__ void __launch_bounds__(256)
attn_mma_kernel(const __nv_bfloat16* __restrict__ qh, const __nv_bfloat16* __restrict__ ql,
                const __nv_bfloat16* __restrict__ kh, const __nv_bfloat16* __restrict__ kl,
                const __nv_bfloat16* __restrict__ vth, const __nv_bfloat16* __restrict__ vtl,
                float* __restrict__ o)
{
    extern __shared__ __align__(16) char sm[];
    const uint32_t su = smem_to_u32(sm);

    const int qb   = gridDim.x - 1 - blockIdx.x;   /* heavy blocks first */
    const int bh   = blockIdx.y;
    const int tid  = threadIdx.x;
    const int lane = tid & 31;
    const int wid  = tid >> 5;                     /* 0..7 */

    const int b = bh >> 4, h = bh & 15;
    const size_t qkrow0 = ((size_t)b * SEQ) * D_MODEL + (size_t)h * 64;
    const size_t vtrow0 = ((size_t)bh * 64) * SEQ;

    /* ---- load Q tile: 128 rows x 64 bf16, hi+lo ---- */
    {
        const int lrow = tid >> 1, lhalf = tid & 1;
        const uint32_t sts = (uint32_t)lrow * AQP + lhalf * 64;
        const size_t g = qkrow0 + (size_t)(qb * 128 + lrow) * D_MODEL + lhalf * 32;
        const uint4* sh = (const uint4*)(qh + g);
        const uint4* sl = (const uint4*)(ql + g);
        uint4* dh = (uint4*)(sm + sts);
        uint4* dl = (uint4*)(sm + AQTILE + sts);
        #pragma unroll
        for (int f = 0; f < 4; f++) { dh[f] = sh[f]; dl[f] = sl[f]; }
    }

    const int nkb = 2 * qb + 2;

    /* cp.async stage issue: 8 x 16B per thread per stage */
    auto issue_stage = [&](int s, int kb) {
        const uint32_t sb = su + 2 * AQTILE + s * ASTAGE;
        #pragma unroll
        for (int i = 0; i < 2; i++) {
            const int idx = tid + i * 256;
            const int row = idx >> 3, c = idx & 7;
            const uint32_t so = (uint32_t)row * AQP + c * 16;
            const size_t gk = qkrow0 + (size_t)(kb * 64 + row) * D_MODEL + c * 8;
            const size_t gv = vtrow0 + (size_t)row * SEQ + kb * 64 + c * 8;
            CP_ASYNC16(sb + 0 * AKTILE + so, kh + gk);
            CP_ASYNC16(sb + 1 * AKTILE + so, kl + gk);
            CP_ASYNC16(sb + 2 * AKTILE + so, vth + gv);
            CP_ASYNC16(sb + 3 * AKTILE + so, vtl + gv);
        }
        CP_COMMIT();
    };

    issue_stage(0, 0);

    const uint32_t a_ld = su + (uint32_t)(wid * 16 + (lane & 15)) * AQP + (lane >> 4) * 16;
    const uint32_t t_ld = su + 2 * AQTILE + (uint32_t)(lane & 15) * AQP + (lane >> 4) * 16;

    float acc[8][4] = {};
    float mo1 = -1e30f, mo2 = -1e30f, l1 = 0.0f, l2 = 0.0f;
    const int q1g = qb * 128 + wid * 16 + (lane >> 2);

    for (int kb = 0; kb < nkb; kb++) {
        const int s = kb & 1;
        if (kb + 1 < nkb) { issue_stage(s ^ 1, kb + 1); CP_WAIT1(); }
        else              { CP_WAIT0(); }
        __syncthreads();

        const uint32_t kb_ld = t_ld + s * ASTAGE;

        /* S = Q @ K^T (split, 3 terms) */
        float sc[8][4] = {};
        #pragma unroll
        for (int ks = 0; ks < 4; ks++) {
            uint32_t ah[4], al[4];
            LDSM_X4(ah[0], ah[1], ah[2], ah[3], a_ld + ks * 32 + 0 * AQTILE);
            LDSM_X4(al[0], al[1], al[2], al[3], a_ld + ks * 32 + 1 * AQTILE);
            #pragma unroll
            for (int nb = 0; nb < 4; nb++) {
                uint32_t r0, r1, r2, r3, q0, q1, q2, q3;
                LDSM_X4(r0, r1, r2, r3, kb_ld + nb * 16 * AQP + ks * 32 + 0 * AKTILE);
                LDSM_X4(q0, q1, q2, q3, kb_ld + nb * 16 * AQP + ks * 32 + 1 * AKTILE);
                uint32_t be[2] = {r0, r2}, bo[2] = {r1, r3};
                uint32_t le[2] = {q0, q2}, lo_[2] = {q1, q3};
                MMA_BF16(sc[2 * nb],     ah, be); MMA_BF16(sc[2 * nb],     ah, le); MMA_BF16(sc[2 * nb],     al, be);
                MMA_BF16(sc[2 * nb + 1], ah, bo); MMA_BF16(sc[2 * nb + 1], ah, lo_); MMA_BF16(sc[2 * nb + 1], al, bo);
            }
        }

        /* causal mask (warp-uniform skip) */
        if (kb * 64 + 63 > qb * 128 + wid * 16) {
            #pragma unroll
            for (int j = 0; j < 8; j++) {
                const int c = kb * 64 + j * 8 + (lane & 3) * 2;
                if (c     > q1g)     sc[j][0] = -1e30f;
                if (c + 1 > q1g)     sc[j][1] = -1e30f;
                if (c     > q1g + 8) sc[j][2] = -1e30f;
                if (c + 1 > q1g + 8) sc[j][3] = -1e30f;
            }
        }

        /* online softmax */
        float m1 = -1e30f, m2 = -1e30f;
        #pragma unroll
        for (int j = 0; j < 8; j++) {
            m1 = fmaxf(m1, fmaxf(sc[j][0], sc[j][1]));
            m2 = fmaxf(m2, fmaxf(sc[j][2], sc[j][3]));
        }
        m1 = fmaxf(m1, __shfl_xor_sync(0xffffffffu, m1, 1));
        m1 = fmaxf(m1, __shfl_xor_sync(0xffffffffu, m1, 2));
        m2 = fmaxf(m2, __shfl_xor_sync(0xffffffffu, m2, 1));
        m2 = fmaxf(m2, __shfl_xor_sync(0xffffffffu, m2, 2));
        const float mn1 = fmaxf(mo1, m1), mn2 = fmaxf(mo2, m2);
        const float sc1 = __expf(mo1 - mn1), sc2 = __expf(mo2 - mn2);
        float sum1 = 0.0f, sum2 = 0.0f;
        #pragma unroll
        for (int j = 0; j < 8; j++) {
            sc[j][0] = __expf(sc[j][0] - mn1); sum1 += sc[j][0];
            sc[j][1] = __expf(sc[j][1] - mn1); sum1 += sc[j][1];
            sc[j][2] = __expf(sc[j][2] - mn2); sum2 += sc[j][2];
            sc[j][3] = __expf(sc[j][3] - mn2); sum2 += sc[j][3];
        }
        sum1 += __shfl_xor_sync(0xffffffffu, sum1, 1);
        sum1 += __shfl_xor_sync(0xffffffffu, sum1, 2);
        sum2 += __shfl_xor_sync(0xffffffffu, sum2, 1);
        sum2 += __shfl_xor_sync(0xffffffffu, sum2, 2);
        l1 = l1 * sc1 + sum1; l2 = l2 * sc2 + sum2;
        mo1 = mn1; mo2 = mn2;
        #pragma unroll
        for (int j = 0; j < 8; j++) {
            acc[j][0] *= sc1; acc[j][1] *= sc1;
            acc[j][2] *= sc2; acc[j][3] *= sc2;
        }

        /* O += P @ V (P from registers, split) */
        #pragma unroll
        for (int ks = 0; ks < 4; ks++) {
            uint32_t ph[4], pl[4];
            #pragma unroll
            for (int t2 = 0; t2 < 2; t2++) {
                const int j = 2 * ks + t2;
                __nv_bfloat16 h0 = __float2bfloat16_rn(sc[j][0]);
                __nv_bfloat16 h1 = __float2bfloat16_rn(sc[j][1]);
                __nv_bfloat16 h2 = __float2bfloat16_rn(sc[j][2]);
                __nv_bfloat16 h3 = __float2bfloat16_rn(sc[j][3]);
                ph[2 * t2]     = pk_bf16x2(h0, h1);
                ph[2 * t2 + 1] = pk_bf16x2(h2, h3);
                pl[2 * t2]     = pk_bf16x2(
                    __float2bfloat16_rn(sc[j][0] - __bfloat162float(h0)),
                    __float2bfloat16_rn(sc[j][1] - __bfloat162float(h1)));
                pl[2 * t2 + 1] = pk_bf16x2(
                    __float2bfloat16_rn(sc[j][2] - __bfloat162float(h2)),
                    __float2bfloat16_rn(sc[j][3] - __bfloat162float(h3)));
            }
            #pragma unroll
            for (int nb = 0; nb < 4; nb++) {
                uint32_t r0, r1, r2, r3, q0, q1, q2, q3;
                LDSM_X4(r0, r1, r2, r3, kb_ld + nb * 16 * AQP + ks * 32 + 2 * AKTILE);
                LDSM_X4(q0, q1, q2, q3, kb_ld + nb * 16 * AQP + ks * 32 + 3 * AKTILE);
                uint32_t be[2] = {r0, r2}, bo[2] = {r1, r3};
                uint32_t le[2] = {q0, q2}, lo_[2] = {q1, q3};
                MMA_BF16(acc[2 * nb],     ph, be); MMA_BF16(acc[2 * nb],     ph, le); MMA_BF16(acc[2 * nb],     pl, be);
                MMA_BF16(acc[2 * nb + 1], ph, bo); MMA_BF16(acc[2 * nb + 1], ph, lo_); MMA_BF16(acc[2 * nb + 1], pl, bo);
            }
        }
        __syncthreads();
    }

    /* epilogue */
    const float i1 = 1.0f / l1, i2 = 1.0f / l2;
    const size_t r1a = qkrow0 + (size_t)(qb * 128 + wid * 16 + (lane >> 2)) * D_MODEL;
    const size_t r2a = r1a + 8 * D_MODEL;
    #pragma unroll
    for (int j = 0; j < 8; j++) {
        const int c = j * 8 + (lane & 3) * 2;
        *(float2*)(o + r1a + c) = make_float2(acc[j][0] * i1, acc[j][1] * i1);
        *(float2*)(o + r2a + c) = make_float2(acc[j][2] * i2, acc[j][3] * i2);
    }
}

/* ============================================================ */
extern "C" void kernel_launch(void* const* d_in, const int* in_sizes, int n_in,
                              void* d_out, int out_size)
{
    const float* x  = (const float*)d_in[0];
    const float* Wq = (const float*)d_in[1];
    const float* Wk = (const float*)d_in[2];
    const float* Wv = (const float*)d_in[3];
    const float* Wo = (const float*)d_in[4];
    float* out = (float*)d_out;

    float *qp, *kp, *vp, *ap;
    __nv_bfloat16 *qhp, *qlp, *khp, *klp, *vthp, *vtlp;
    cudaGetSymbolAddress((void**)&qp, g_q);
    cudaGetSymbolAddress((void**)&kp, g_k);
    cudaGetSymbolAddress((void**)&vp, g_v);
    cudaGetSymbolAddress((void**)&ap, g_a);
    cudaGetSymbolAddress((void**)&qhp, g_qh);
    cudaGetSymbolAddress((void**)&qlp, g_ql);
    cudaGetSymbolAddress((void**)&khp, g_kh);
    cudaGetSymbolAddress((void**)&klp, g_kl);
    cudaGetSymbolAddress((void**)&vthp, g_vth);
    cudaGetSymbolAddress((void**)&vtlp, g_vtl);

    static bool attr_done = false;
    if (!attr_done) {
        cudaFuncSetAttribute(gemm_mma_kernel,
                             cudaFuncAttributeMaxDynamicSharedMemorySize, GEMM_SMEM);
        cudaFuncSetAttribute(attn_mma_kernel,
                             cudaFuncAttributeMaxDynamicSharedMemorySize, ATTN_SMEM);
        attr_done = true;
    }

    const dim3 gg(D_MODEL / BN, M_TOT / BM);

    gemm_mma_kernel<<<gg, 256, GEMM_SMEM>>>(x, Wq, qp, M_TOT, D_MODEL, D_MODEL);
    gemm_mma_kernel<<<gg, 256, GEMM_SMEM>>>(x, Wk, kp, M_TOT, D_MODEL, D_MODEL);
    gemm_mma_kernel<<<gg, 256, GEMM_SMEM>>>(x, Wv, vp, M_TOT, D_MODEL, D_MODEL);

    rope2_kernel<<<M_TOT / 8, 256>>>(qp, kp, qhp, qlp, khp, klp);
    vtrans_kernel<<<dim3(SEQ / 64, BATCH * N_HEADS), 256>>>(vp, vthp, vtlp);

    attn_mma_kernel<<<dim3(SEQ / 128, BATCH * N_HEADS), 256, ATTN_SMEM>>>(
        qhp, qlp, khp, klp, vthp, vtlp, ap);

    gemm_mma_kernel<<<gg, 256, GEMM_SMEM>>>(ap, Wo, out, M_TOT, D_MODEL, D_MODEL);
}

// round 8
// speedup vs baseline: 2.8748x; 1.1512x over previous
#include <cuda_runtime.h>
#include <cuda_bf16.h>
#include <math.h>
#include <stdint.h>

#define D_MODEL 1024
#define N_HEADS 16
#define HEAD_DIM 64
#define BATCH 2
#define SEQ 2048
#define M_TOT (BATCH * SEQ)   /* 4096 */

/* ---- scratch (allocation-free: __device__ globals) ---- */
__device__ float g_q[(size_t)M_TOT * D_MODEL];
__device__ float g_k[(size_t)M_TOT * D_MODEL];
__device__ float g_v[(size_t)M_TOT * D_MODEL];
/* pre-split bf16 buffers */
__device__ __nv_bfloat16 g_xh[(size_t)M_TOT * D_MODEL];
__device__ __nv_bfloat16 g_xl[(size_t)M_TOT * D_MODEL];
__device__ __nv_bfloat16 g_wh[4][(size_t)D_MODEL * D_MODEL];
__device__ __nv_bfloat16 g_wl[4][(size_t)D_MODEL * D_MODEL];
__device__ __nv_bfloat16 g_qh[(size_t)M_TOT * D_MODEL];
__device__ __nv_bfloat16 g_ql[(size_t)M_TOT * D_MODEL];
__device__ __nv_bfloat16 g_kh[(size_t)M_TOT * D_MODEL];
__device__ __nv_bfloat16 g_kl[(size_t)M_TOT * D_MODEL];
__device__ __nv_bfloat16 g_vth[(size_t)M_TOT * D_MODEL];  /* [bh][d][S] */
__device__ __nv_bfloat16 g_vtl[(size_t)M_TOT * D_MODEL];
__device__ __nv_bfloat16 g_oh[(size_t)M_TOT * D_MODEL];
__device__ __nv_bfloat16 g_ol[(size_t)M_TOT * D_MODEL];

__device__ __forceinline__ uint32_t smem_to_u32(const void* p) {
    uint32_t a;
    asm("{ .reg .u64 t; cvta.to.shared.u64 t, %1; cvt.u32.u64 %0, t; }" : "=r"(a) : "l"(p));
    return a;
}

#define LDSM_X4(r0, r1, r2, r3, addr) \
    asm volatile("ldmatrix.sync.aligned.m8n8.x4.shared.b16 {%0,%1,%2,%3}, [%4];" \
                 : "=r"(r0), "=r"(r1), "=r"(r2), "=r"(r3) : "r"(addr))

#define MMA_BF16(c, a, b) \
    asm volatile("mma.sync.aligned.m16n8k16.row.col.f32.bf16.bf16.f32 " \
                 "{%0,%1,%2,%3},{%4,%5,%6,%7},{%8,%9},{%0,%1,%2,%3};" \
                 : "+f"((c)[0]), "+f"((c)[1]), "+f"((c)[2]), "+f"((c)[3]) \
                 : "r"((a)[0]), "r"((a)[1]), "r"((a)[2]), "r"((a)[3]), \
                   "r"((b)[0]), "r"((b)[1]))

#define CP_ASYNC16(saddr, gptr) \
    asm volatile("cp.async.cg.shared.global [%0], [%1], 16;" \
                 :: "r"(saddr), "l"(gptr) : "memory")
#define CP_COMMIT() asm volatile("cp.async.commit_group;" ::: "memory")
#define CP_WAIT0()  asm volatile("cp.async.wait_group 0;" ::: "memory")
#define CP_WAIT1()  asm volatile("cp.async.wait_group 1;" ::: "memory")

__device__ __forceinline__ uint32_t pk_bf16x2(__nv_bfloat16 a, __nv_bfloat16 b) {
    return (uint32_t)__bfloat16_as_ushort(a) | ((uint32_t)__bfloat16_as_ushort(b) << 16);
}

__device__ __forceinline__ void split4(float4 v, uint2& hi, uint2& lo) {
    __nv_bfloat16 h0 = __float2bfloat16_rn(v.x), h1 = __float2bfloat16_rn(v.y);
    __nv_bfloat16 h2 = __float2bfloat16_rn(v.z), h3 = __float2bfloat16_rn(v.w);
    __nv_bfloat16 l0 = __float2bfloat16_rn(v.x - __bfloat162float(h0));
    __nv_bfloat16 l1 = __float2bfloat16_rn(v.y - __bfloat162float(h1));
    __nv_bfloat16 l2 = __float2bfloat16_rn(v.z - __bfloat162float(h2));
    __nv_bfloat16 l3 = __float2bfloat16_rn(v.w - __bfloat162float(h3));
    hi = make_uint2(pk_bf16x2(h0, h1), pk_bf16x2(h2, h3));
    lo = make_uint2(pk_bf16x2(l0, l1), pk_bf16x2(l2, l3));
}

/* ============================================================
 * fp32 -> bf16 hi/lo split (memory-bound, 4 elems/thread).
 * ============================================================ */
__global__ void __launch_bounds__(256)
split_kernel(const float* __restrict__ in,
             __nv_bfloat16* __restrict__ oh, __nv_bfloat16* __restrict__ ol)
{
    const size_t i = ((size_t)blockIdx.x * 256 + threadIdx.x) * 4;
    float4 v = *(const float4*)(in + i);
    uint2 hi, lo;
    split4(v, hi, lo);
    *(uint2*)(oh + i) = hi;
    *(uint2*)(ol + i) = lo;
}

/* ============================================================
 * Split-bf16 GEMM on pre-split inputs, cp.async double-buffered.
 * C[M,N] = (Ah+Al)[M,K] @ (Bh+Bl)[N,K]^T  (3-term split, fp32 C)
 * CTA 128x128, BK=32, 8 warps (2x4), warp tile 64x32.
 * ============================================================ */
#define GBK 32
#define GP 80                 /* 64B data + 16B pad per 32-bf16 row */
#define GT (128 * GP)         /* 10240 per tile */
#define GSTG (4 * GT)         /* Ah, Al, Bh, Bl = 40960 */
#define GEMM_SMEM (2 * GSTG)  /* 81920 */

__global__ void __launch_bounds__(256)
gemm_bs_kernel(const __nv_bfloat16* __restrict__ Ah, const __nv_bfloat16* __restrict__ Al,
               const __nv_bfloat16* __restrict__ Bh, const __nv_bfloat16* __restrict__ Bl,
               float* __restrict__ C, int M, int N, int K)
{
    extern __shared__ __align__(16) char smem[];
    const uint32_t su = smem_to_u32(smem);

    const int tid    = threadIdx.x;
    const int lane   = tid & 31;
    const int wid    = tid >> 5;
    const int warp_m = wid >> 2;
    const int warp_n = wid & 3;
    const int m0 = blockIdx.y * 128;
    const int n0 = blockIdx.x * 128;

    const int nchunks = K / GBK;   /* 32 */

    /* cp.async stage: 4 tiles x 128 rows x 4 x 16B = 2048 xfers, 8/thread */
    auto issue_stage = [&](int s, int i) {
        const uint32_t sb = su + s * GSTG;
        #pragma unroll
        for (int t = 0; t < 2; t++) {
            const int idx = tid + t * 256;          /* 0..511 */
            const int row = idx >> 2, c = idx & 3;
            const uint32_t so = (uint32_t)row * GP + c * 16;
            const size_t ga = (size_t)(m0 + row) * K + i * GBK + c * 8;
            const size_t gb = (size_t)(n0 + row) * K + i * GBK + c * 8;
            CP_ASYNC16(sb + 0 * GT + so, Ah + ga);
            CP_ASYNC16(sb + 1 * GT + so, Al + ga);
            CP_ASYNC16(sb + 2 * GT + so, Bh + gb);
            CP_ASYNC16(sb + 3 * GT + so, Bl + gb);
        }
        CP_COMMIT();
    };

    issue_stage(0, 0);

    const uint32_t a_ld = su + (uint32_t)(warp_m * 64 + (lane & 15)) * GP + (lane >> 4) * 16;
    const uint32_t b_ld = su + (uint32_t)(warp_n * 32 + (lane & 15)) * GP + (lane >> 4) * 16;

    float acc[4][4][4] = {};

    for (int i = 0; i < nchunks; i++) {
        const int s = i & 1;
        if (i + 1 < nchunks) { issue_stage(s ^ 1, i + 1); CP_WAIT1(); }
        else                 { CP_WAIT0(); }
        __syncthreads();

        const uint32_t stb = s * GSTG;
        #pragma unroll
        for (int ks = 0; ks < 2; ks++) {
            uint32_t ah[4][4], al[4][4], bh[4][2], bl[4][2];
            #pragma unroll
            for (int mt = 0; mt < 4; mt++) {
                LDSM_X4(ah[mt][0], ah[mt][1], ah[mt][2], ah[mt][3],
                        a_ld + stb + 0 * GT + mt * 16 * GP + ks * 32);
                LDSM_X4(al[mt][0], al[mt][1], al[mt][2], al[mt][3],
                        a_ld + stb + 1 * GT + mt * 16 * GP + ks * 32);
            }
            #pragma unroll
            for (int nb = 0; nb < 2; nb++) {
                uint32_t r0, r1, r2, r3;
                LDSM_X4(r0, r1, r2, r3,
                        b_ld + stb + 2 * GT + nb * 16 * GP + ks * 32);
                bh[nb * 2][0] = r0; bh[nb * 2][1] = r2;
                bh[nb * 2 + 1][0] = r1; bh[nb * 2 + 1][1] = r3;
                LDSM_X4(r0, r1, r2, r3,
                        b_ld + stb + 3 * GT + nb * 16 * GP + ks * 32);
                bl[nb * 2][0] = r0; bl[nb * 2][1] = r2;
                bl[nb * 2 + 1][0] = r1; bl[nb * 2 + 1][1] = r3;
            }
            #pragma unroll
            for (int mt = 0; mt < 4; mt++)
                #pragma unroll
                for (int nt = 0; nt < 4; nt++) {
                    MMA_BF16(acc[mt][nt], ah[mt], bh[nt]);
                    MMA_BF16(acc[mt][nt], ah[mt], bl[nt]);
                    MMA_BF16(acc[mt][nt], al[mt], bh[nt]);
                }
        }
        __syncthreads();
    }

    #pragma unroll
    for (int mt = 0; mt < 4; mt++) {
        const int m = m0 + warp_m * 64 + mt * 16 + (lane >> 2);
        #pragma unroll
        for (int nt = 0; nt < 4; nt++) {
            const int n = n0 + warp_n * 32 + nt * 8 + (lane & 3) * 2;
            *(float2*)(C + (size_t)m * N + n) =
                make_float2(acc[mt][nt][0], acc[mt][nt][1]);
            *(float2*)(C + (size_t)(m + 8) * N + n) =
                make_float2(acc[mt][nt][2], acc[mt][nt][3]);
        }
    }
}

/* ============================================================
 * Fused RoPE for Q and K (sincos computed once per position).
 * ============================================================ */
__global__ void __launch_bounds__(256)
rope2_kernel(const float* __restrict__ q, const float* __restrict__ k,
             __nv_bfloat16* __restrict__ qh, __nv_bfloat16* __restrict__ ql,
             __nv_bfloat16* __restrict__ kh, __nv_bfloat16* __restrict__ kl)
{
    __shared__ float invf[32];
    const int tid = threadIdx.x;
    if (tid < 32) invf[tid] = (float)pow(10000.0, -(double)tid / 32.0);
    __syncthreads();

    const int bs   = blockIdx.x * 8 + (tid >> 5);
    const int lane = tid & 31;
    const int pos  = bs & (SEQ - 1);

    float s1, c1, s2, c2;
    sincosf((float)pos * invf[(2 * lane) & 31],     &s1, &c1);
    sincosf((float)pos * invf[(2 * lane + 1) & 31], &s2, &c2);

    const size_t base = (size_t)bs * D_MODEL;
    #pragma unroll
    for (int h = 0; h < N_HEADS; h++) {
        const size_t ro = base + h * 64;
        {
            float x0 = q[ro + 2 * lane], x1 = q[ro + 2 * lane + 1];
            float y0 = (x0 * c1 - x1 * s1) * 0.125f;
            float y1 = (x0 * s2 + x1 * c2) * 0.125f;
            __nv_bfloat16 h0 = __float2bfloat16_rn(y0);
            __nv_bfloat16 h1 = __float2bfloat16_rn(y1);
            qh[ro + lane]      = h0;
            ql[ro + lane]      = __float2bfloat16_rn(y0 - __bfloat162float(h0));
            qh[ro + 32 + lane] = h1;
            ql[ro + 32 + lane] = __float2bfloat16_rn(y1 - __bfloat162float(h1));
        }
        {
            float x0 = k[ro + 2 * lane], x1 = k[ro + 2 * lane + 1];
            float y0 = x0 * c1 - x1 * s1;
            float y1 = x0 * s2 + x1 * c2;
            __nv_bfloat16 h0 = __float2bfloat16_rn(y0);
            __nv_bfloat16 h1 = __float2bfloat16_rn(y1);
            kh[ro + lane]      = h0;
            kl[ro + lane]      = __float2bfloat16_rn(y0 - __bfloat162float(h0));
            kh[ro + 32 + lane] = h1;
            kl[ro + 32 + lane] = __float2bfloat16_rn(y1 - __bfloat162float(h1));
        }
    }
}

/* ============================================================
 * V transpose + split (unchanged).
 * ============================================================ */
__global__ void __launch_bounds__(256)
vtrans_kernel(const float* __restrict__ v,
              __nv_bfloat16* __restrict__ vth, __nv_bfloat16* __restrict__ vtl)
{
    __shared__ float t[64][65];
    const int sblk = blockIdx.x;
    const int bh   = blockIdx.y;
    const int tid  = threadIdx.x;

    {
        const int row = tid >> 2;
        const int c0  = (tid & 3) * 16;
        const size_t gaddr = ((size_t)(bh >> 4) * SEQ + sblk * 64 + row) * D_MODEL
                           + (bh & 15) * 64 + c0;
        #pragma unroll
        for (int f = 0; f < 4; f++) {
            float4 vv = *(const float4*)(v + gaddr + f * 4);
            t[row][c0 + f * 4 + 0] = vv.x; t[row][c0 + f * 4 + 1] = vv.y;
            t[row][c0 + f * 4 + 2] = vv.z; t[row][c0 + f * 4 + 3] = vv.w;
        }
    }
    __syncthreads();

    const int d  = tid >> 2;
    const int k0 = (tid & 3) * 16;
    __nv_bfloat16 hv[16], lv[16];
    #pragma unroll
    for (int kk = 0; kk < 16; kk++) {
        float x = t[k0 + kk][d];
        hv[kk] = __float2bfloat16_rn(x);
        lv[kk] = __float2bfloat16_rn(x - __bfloat162float(hv[kk]));
    }
    const size_t dst = ((size_t)bh * 64 + d) * SEQ + sblk * 64 + k0;
    *(uint4*)(vth + dst)     = *(uint4*)(hv);
    *(uint4*)(vth + dst + 8) = *(uint4*)(hv + 8);
    *(uint4*)(vtl + dst)     = *(uint4*)(lv);
    *(uint4*)(vtl + dst + 8) = *(uint4*)(lv + 8);
}

/* ============================================================
 * Flash attention, causal, split-bf16 mma.sync, cp.async pipeline.
 * Block = 128 q-rows of one (b,h), 8 warps. Output bf16 hi/lo.
 * ============================================================ */
#define AQP 144
#define AQTILE (128 * AQP)
#define AKTILE (64 * AQP)
#define ASTAGE (4 * AKTILE)
#define ATTN_SMEM (2 * AQTILE + 2 * ASTAGE)  /* 110592 */

__global__ void __launch_bounds__(256)
attn_mma_kernel(const __nv_bfloat16* __restrict__ qh, const __nv_bfloat16* __restrict__ ql,
                const __nv_bfloat16* __restrict__ kh, const __nv_bfloat16* __restrict__ kl,
                const __nv_bfloat16* __restrict__ vth, const __nv_bfloat16* __restrict__ vtl,
                __nv_bfloat16* __restrict__ oh, __nv_bfloat16* __restrict__ ol)
{
    extern __shared__ __align__(16) char sm[];
    const uint32_t su = smem_to_u32(sm);

    const int qb   = gridDim.x - 1 - blockIdx.x;
    const int bh   = blockIdx.y;
    const int tid  = threadIdx.x;
    const int lane = tid & 31;
    const int wid  = tid >> 5;

    const int b = bh >> 4, h = bh & 15;
    const size_t qkrow0 = ((size_t)b * SEQ) * D_MODEL + (size_t)h * 64;
    const size_t vtrow0 = ((size_t)bh * 64) * SEQ;

    {
        const int lrow = tid >> 1, lhalf = tid & 1;
        const uint32_t sts = (uint32_t)lrow * AQP + lhalf * 64;
        const size_t g = qkrow0 + (size_t)(qb * 128 + lrow) * D_MODEL + lhalf * 32;
        const uint4* sh = (const uint4*)(qh + g);
        const uint4* sl = (const uint4*)(ql + g);
        uint4* dh = (uint4*)(sm + sts);
        uint4* dl = (uint4*)(sm + AQTILE + sts);
        #pragma unroll
        for (int f = 0; f < 4; f++) { dh[f] = sh[f]; dl[f] = sl[f]; }
    }

    const int nkb = 2 * qb + 2;

    auto issue_stage = [&](int s, int kb) {
        const uint32_t sb = su + 2 * AQTILE + s * ASTAGE;
        #pragma unroll
        for (int i = 0; i < 2; i++) {
            const int idx = tid + i * 256;
            const int row = idx >> 3, c = idx & 7;
            const uint32_t so = (uint32_t)row * AQP + c * 16;
            const size_t gk = qkrow0 + (size_t)(kb * 64 + row) * D_MODEL + c * 8;
            const size_t gv = vtrow0 + (size_t)row * SEQ + kb * 64 + c * 8;
            CP_ASYNC16(sb + 0 * AKTILE + so, kh + gk);
            CP_ASYNC16(sb + 1 * AKTILE + so, kl + gk);
            CP_ASYNC16(sb + 2 * AKTILE + so, vth + gv);
            CP_ASYNC16(sb + 3 * AKTILE + so, vtl + gv);
        }
        CP_COMMIT();
    };

    issue_stage(0, 0);

    const uint32_t a_ld = su + (uint32_t)(wid * 16 + (lane & 15)) * AQP + (lane >> 4) * 16;
    const uint32_t t_ld = su + 2 * AQTILE + (uint32_t)(lane & 15) * AQP + (lane >> 4) * 16;

    float acc[8][4] = {};
    float mo1 = -1e30f, mo2 = -1e30f, l1 = 0.0f, l2 = 0.0f;
    const int q1g = qb * 128 + wid * 16 + (lane >> 2);

    for (int kb = 0; kb < nkb; kb++) {
        const int s = kb & 1;
        if (kb + 1 < nkb) { issue_stage(s ^ 1, kb + 1); CP_WAIT1(); }
        else              { CP_WAIT0(); }
        __syncthreads();

        const uint32_t kb_ld = t_ld + s * ASTAGE;

        float sc[8][4] = {};
        #pragma unroll
        for (int ks = 0; ks < 4; ks++) {
            uint32_t ah[4], al[4];
            LDSM_X4(ah[0], ah[1], ah[2], ah[3], a_ld + ks * 32 + 0 * AQTILE);
            LDSM_X4(al[0], al[1], al[2], al[3], a_ld + ks * 32 + 1 * AQTILE);
            #pragma unroll
            for (int nb = 0; nb < 4; nb++) {
                uint32_t r0, r1, r2, r3, q0, q1, q2, q3;
                LDSM_X4(r0, r1, r2, r3, kb_ld + nb * 16 * AQP + ks * 32 + 0 * AKTILE);
                LDSM_X4(q0, q1, q2, q3, kb_ld + nb * 16 * AQP + ks * 32 + 1 * AKTILE);
                uint32_t be[2] = {r0, r2}, bo[2] = {r1, r3};
                uint32_t le[2] = {q0, q2}, lo_[2] = {q1, q3};
                MMA_BF16(sc[2 * nb],     ah, be); MMA_BF16(sc[2 * nb],     ah, le); MMA_BF16(sc[2 * nb],     al, be);
                MMA_BF16(sc[2 * nb + 1], ah, bo); MMA_BF16(sc[2 * nb + 1], ah, lo_); MMA_BF16(sc[2 * nb + 1], al, bo);
            }
        }

        if (kb * 64 + 63 > qb * 128 + wid * 16) {
            #pragma unroll
            for (int j = 0; j < 8; j++) {
                const int c = kb * 64 + j * 8 + (lane & 3) * 2;
                if (c     > q1g)     sc[j][0] = -1e30f;
                if (c + 1 > q1g)     sc[j][1] = -1e30f;
                if (c     > q1g + 8) sc[j][2] = -1e30f;
                if (c + 1 > q1g + 8) sc[j][3] = -1e30f;
            }
        }

        float m1 = -1e30f, m2 = -1e30f;
        #pragma unroll
        for (int j = 0; j < 8; j++) {
            m1 = fmaxf(m1, fmaxf(sc[j][0], sc[j][1]));
            m2 = fmaxf(m2, fmaxf(sc[j][2], sc[j][3]));
        }
        m1 = fmaxf(m1, __shfl_xor_sync(0xffffffffu, m1, 1));
        m1 = fmaxf(m1, __shfl_xor_sync(0xffffffffu, m1, 2));
        m2 = fmaxf(m2, __shfl_xor_sync(0xffffffffu, m2, 1));
        m2 = fmaxf(m2, __shfl_xor_sync(0xffffffffu, m2, 2));
        const float mn1 = fmaxf(mo1, m1), mn2 = fmaxf(mo2, m2);
        const float sc1 = __expf(mo1 - mn1), sc2 = __expf(mo2 - mn2);
        float sum1 = 0.0f, sum2 = 0.0f;
        #pragma unroll
        for (int j = 0; j < 8; j++) {
            sc[j][0] = __expf(sc[j][0] - mn1); sum1 += sc[j][0];
            sc[j][1] = __expf(sc[j][1] - mn1); sum1 += sc[j][1];
            sc[j][2] = __expf(sc[j][2] - mn2); sum2 += sc[j][2];
            sc[j][3] = __expf(sc[j][3] - mn2); sum2 += sc[j][3];
        }
        sum1 += __shfl_xor_sync(0xffffffffu, sum1, 1);
        sum1 += __shfl_xor_sync(0xffffffffu, sum1, 2);
        sum2 += __shfl_xor_sync(0xffffffffu, sum2, 1);
        sum2 += __shfl_xor_sync(0xffffffffu, sum2, 2);
        l1 = l1 * sc1 + sum1; l2 = l2 * sc2 + sum2;
        mo1 = mn1; mo2 = mn2;
        #pragma unroll
        for (int j = 0; j < 8; j++) {
            acc[j][0] *= sc1; acc[j][1] *= sc1;
            acc[j][2] *= sc2; acc[j][3] *= sc2;
        }

        #pragma unroll
        for (int ks = 0; ks < 4; ks++) {
            uint32_t ph[4], pl[4];
            #pragma unroll
            for (int t2 = 0; t2 < 2; t2++) {
                const int j = 2 * ks + t2;
                __nv_bfloat16 h0 = __float2bfloat16_rn(sc[j][0]);
                __nv_bfloat16 h1 = __float2bfloat16_rn(sc[j][1]);
                __nv_bfloat16 h2 = __float2bfloat16_rn(sc[j][2]);
                __nv_bfloat16 h3 = __float2bfloat16_rn(sc[j][3]);
                ph[2 * t2]     = pk_bf16x2(h0, h1);
                ph[2 * t2 + 1] = pk_bf16x2(h2, h3);
                pl[2 * t2]     = pk_bf16x2(
                    __float2bfloat16_rn(sc[j][0] - __bfloat162float(h0)),
                    __float2bfloat16_rn(sc[j][1] - __bfloat162float(h1)));
                pl[2 * t2 + 1] = pk_bf16x2(
                    __float2bfloat16_rn(sc[j][2] - __bfloat162float(h2)),
                    __float2bfloat16_rn(sc[j][3] - __bfloat162float(h3)));
            }
            #pragma unroll
            for (int nb = 0; nb < 4; nb++) {
                uint32_t r0, r1, r2, r3, q0, q1, q2, q3;
                LDSM_X4(r0, r1, r2, r3, kb_ld + nb * 16 * AQP + ks * 32 + 2 * AKTILE);
                LDSM_X4(q0, q1, q2, q3, kb_ld + nb * 16 * AQP + ks * 32 + 3 * AKTILE);
                uint32_t be[2] = {r0, r2}, bo[2] = {r1, r3};
                uint32_t le[2] = {q0, q2}, lo_[2] = {q1, q3};
                MMA_BF16(acc[2 * nb],     ph, be); MMA_BF16(acc[2 * nb],     ph, le); MMA_BF16(acc[2 * nb],     pl, be);
                MMA_BF16(acc[2 * nb + 1], ph, bo); MMA_BF16(acc[2 * nb + 1], ph, lo_); MMA_BF16(acc[2 * nb + 1], pl, bo);
            }
        }
        __syncthreads();
    }

    /* epilogue: normalize, split to bf16 hi/lo, store */
    const float i1 = 1.0f / l1, i2 = 1.0f / l2;
    const size_t r1a = qkrow0 + (size_t)(qb * 128 + wid * 16 + (lane >> 2)) * D_MODEL;
    const size_t r2a = r1a + 8 * D_MODEL;
    #pragma unroll
    for (int j = 0; j < 8; j++) {
        const int c = j * 8 + (lane & 3) * 2;
        float v0 = acc[j][0] * i1, v1 = acc[j][1] * i1;
        float v2 = acc[j][2] * i2, v3 = acc[j][3] * i2;
        __nv_bfloat16 h0 = __float2bfloat16_rn(v0), h1 = __float2bfloat16_rn(v1);
        __nv_bfloat16 h2 = __float2bfloat16_rn(v2), h3 = __float2bfloat16_rn(v3);
        *(uint32_t*)(oh + r1a + c) = pk_bf16x2(h0, h1);
        *(uint32_t*)(ol + r1a + c) = pk_bf16x2(
            __float2bfloat16_rn(v0 - __bfloat162float(h0)),
            __float2bfloat16_rn(v1 - __bfloat162float(h1)));
        *(uint32_t*)(oh + r2a + c) = pk_bf16x2(h2, h3);
        *(uint32_t*)(ol + r2a + c) = pk_bf16x2(
            __float2bfloat16_rn(v2 - __bfloat162float(h2)),
            __float2bfloat16_rn(v3 - __bfloat162float(h3)));
    }
}

/* ============================================================ */
extern "C" void kernel_launch(void* const* d_in, const int* in_sizes, int n_in,
                              void* d_out, int out_size)
{
    const float* x  = (const float*)d_in[0];
    const float* W[4] = { (const float*)d_in[1], (const float*)d_in[2],
                          (const float*)d_in[3], (const float*)d_in[4] };
    float* out = (float*)d_out;

    float *qp, *kp, *vp;
    __nv_bfloat16 *xh, *xl, *wh, *wl, *qhp, *qlp, *khp, *klp, *vthp, *vtlp, *ohp, *olp;
    cudaGetSymbolAddress((void**)&qp, g_q);
    cudaGetSymbolAddress((void**)&kp, g_k);
    cudaGetSymbolAddress((void**)&vp, g_v);
    cudaGetSymbolAddress((void**)&xh, g_xh);
    cudaGetSymbolAddress((void**)&xl, g_xl);
    cudaGetSymbolAddress((void**)&wh, g_wh);
    cudaGetSymbolAddress((void**)&wl, g_wl);
    cudaGetSymbolAddress((void**)&qhp, g_qh);
    cudaGetSymbolAddress((void**)&qlp, g_ql);
    cudaGetSymbolAddress((void**)&khp, g_kh);
    cudaGetSymbolAddress((void**)&klp, g_kl);
    cudaGetSymbolAddress((void**)&vthp, g_vth);
    cudaGetSymbolAddress((void**)&vtlp, g_vtl);
    cudaGetSymbolAddress((void**)&ohp, g_oh);
    cudaGetSymbolAddress((void**)&olp, g_ol);

    static bool attr_done = false;
    if (!attr_done) {
        cudaFuncSetAttribute(gemm_bs_kernel,
                             cudaFuncAttributeMaxDynamicSharedMemorySize, GEMM_SMEM);
        cudaFuncSetAttribute(attn_mma_kernel,
                             cudaFuncAttributeMaxDynamicSharedMemorySize, ATTN_SMEM);
        attr_done = true;
    }

    const size_t WSZ = (size_t)D_MODEL * D_MODEL;

    /* pre-split x and weights */
    split_kernel<<<M_TOT * D_MODEL / 1024, 256>>>(x, xh, xl);
    for (int i = 0; i < 4; i++)
        split_kernel<<<WSZ / 1024, 256>>>(W[i], wh + i * WSZ, wl + i * WSZ);

    const dim3 gg(D_MODEL / 128, M_TOT / 128);   /* (8, 32) */

    gemm_bs_kernel<<<gg, 256, GEMM_SMEM>>>(xh, xl, wh + 0 * WSZ, wl + 0 * WSZ,
                                           qp, M_TOT, D_MODEL, D_MODEL);
    gemm_bs_kernel<<<gg, 256, GEMM_SMEM>>>(xh, xl, wh + 1 * WSZ, wl + 1 * WSZ,
                                           kp, M_TOT, D_MODEL, D_MODEL);
    gemm_bs_kernel<<<gg, 256, GEMM_SMEM>>>(xh, xl, wh + 2 * WSZ, wl + 2 * WSZ,
                                           vp, M_TOT, D_MODEL, D_MODEL);

    rope2_kernel<<<M_TOT / 8, 256>>>(qp, kp, qhp, qlp, khp, klp);
    vtrans_kernel<<<dim3(SEQ / 64, BATCH * N_HEADS), 256>>>(vp, vthp, vtlp);

    attn_mma_kernel<<<dim3(SEQ / 128, BATCH * N_HEADS), 256, ATTN_SMEM>>>(
        qhp, qlp, khp, klp, vthp, vtlp, ohp, olp);

    gemm_bs_kernel<<<gg, 256, GEMM_SMEM>>>(ohp, olp, wh + 3 * WSZ, wl + 3 * WSZ,
                                           out, M_TOT, D_MODEL, D_MODEL);
}

// round 9
// speedup vs baseline: 3.6290x; 1.2623x over previous
#include <cuda_runtime.h>
#include <cuda_bf16.h>
#include <math.h>
#include <stdint.h>

#define D_MODEL 1024
#define N_HEADS 16
#define HEAD_DIM 64
#define BATCH 2
#define SEQ 2048
#define M_TOT (BATCH * SEQ)   /* 4096 */

/* ---- scratch (allocation-free: __device__ globals) ---- */
__device__ float g_q[(size_t)M_TOT * D_MODEL];   /* q, later reused as O */
__device__ float g_k[(size_t)M_TOT * D_MODEL];
__device__ float g_v[(size_t)M_TOT * D_MODEL];
__device__ float g_xr[(size_t)M_TOT * D_MODEL];          /* tf32-rounded x */
__device__ float g_wr[4][(size_t)D_MODEL * D_MODEL];     /* tf32-rounded W */
__device__ __nv_bfloat16 g_qh[(size_t)M_TOT * D_MODEL];
__device__ __nv_bfloat16 g_ql[(size_t)M_TOT * D_MODEL];
__device__ __nv_bfloat16 g_kh[(size_t)M_TOT * D_MODEL];
__device__ __nv_bfloat16 g_kl[(size_t)M_TOT * D_MODEL];
__device__ __nv_bfloat16 g_vth[(size_t)M_TOT * D_MODEL]; /* [bh][d][S] */
__device__ __nv_bfloat16 g_vtl[(size_t)M_TOT * D_MODEL];

__device__ __forceinline__ uint32_t smem_to_u32(const void* p) {
    uint32_t a;
    asm("{ .reg .u64 t; cvta.to.shared.u64 t, %1; cvt.u32.u64 %0, t; }" : "=r"(a) : "l"(p));
    return a;
}

#define LDSM_X4(r0, r1, r2, r3, addr) \
    asm volatile("ldmatrix.sync.aligned.m8n8.x4.shared.b16 {%0,%1,%2,%3}, [%4];" \
                 : "=r"(r0), "=r"(r1), "=r"(r2), "=r"(r3) : "r"(addr))

#define MMA_BF16(c, a, b) \
    asm volatile("mma.sync.aligned.m16n8k16.row.col.f32.bf16.bf16.f32 " \
                 "{%0,%1,%2,%3},{%4,%5,%6,%7},{%8,%9},{%0,%1,%2,%3};" \
                 : "+f"((c)[0]), "+f"((c)[1]), "+f"((c)[2]), "+f"((c)[3]) \
                 : "r"((a)[0]), "r"((a)[1]), "r"((a)[2]), "r"((a)[3]), \
                   "r"((b)[0]), "r"((b)[1]))

#define MMA_TF32(c, a, b) \
    asm volatile("mma.sync.aligned.m16n8k8.row.col.f32.tf32.tf32.f32 " \
                 "{%0,%1,%2,%3},{%4,%5,%6,%7},{%8,%9},{%0,%1,%2,%3};" \
                 : "+f"((c)[0]), "+f"((c)[1]), "+f"((c)[2]), "+f"((c)[3]) \
                 : "r"((a)[0]), "r"((a)[1]), "r"((a)[2]), "r"((a)[3]), \
                   "r"((b)[0]), "r"((b)[1]))

#define CP_ASYNC16(saddr, gptr) \
    asm volatile("cp.async.cg.shared.global [%0], [%1], 16;" \
                 :: "r"(saddr), "l"(gptr) : "memory")
#define CP_COMMIT() asm volatile("cp.async.commit_group;" ::: "memory")
#define CP_WAIT0()  asm volatile("cp.async.wait_group 0;" ::: "memory")
#define CP_WAIT1()  asm volatile("cp.async.wait_group 1;" ::: "memory")

__device__ __forceinline__ uint32_t pk_bf16x2(__nv_bfloat16 a, __nv_bfloat16 b) {
    return (uint32_t)__bfloat16_as_ushort(a) | ((uint32_t)__bfloat16_as_ushort(b) << 16);
}
__device__ __forceinline__ float tf32r(float x) {
    uint32_t r;
    asm("cvt.rna.tf32.f32 %0, %1;" : "=r"(r) : "f"(x));
    return __uint_as_float(r);
}

/* ============================================================
 * fp32 -> tf32-rounded fp32 (memory-bound).
 * ============================================================ */
__global__ void __launch_bounds__(256)
round_kernel(const float* __restrict__ in, float* __restrict__ out)
{
    const size_t i = ((size_t)blockIdx.x * 256 + threadIdx.x) * 4;
    float4 v = *(const float4*)(in + i);
    v.x = tf32r(v.x); v.y = tf32r(v.y); v.z = tf32r(v.z); v.w = tf32r(v.w);
    *(float4*)(out + i) = v;
}

/* ============================================================
 * tf32 single-pass GEMM: C[M,N] = A[M,K] @ B[N,K]^T (fp32 io,
 * inputs pre-rounded to tf32). CTA 128x128, BK=32, 8 warps (2x4),
 * warp tile 64x32, mma.m16n8k8. cp.async double-buffered.
 * Smem pitch 36 floats (144B) -> conflict-free quad frag loads.
 * ============================================================ */
#define TPAD 144              /* bytes per 32-float row */
#define TTILE (128 * TPAD)    /* 18432 */
#define TSTG (2 * TTILE)      /* A + B = 36864 */
#define GEMM_SMEM (2 * TSTG)  /* 73728 */

__global__ void __launch_bounds__(256, 2)
gemm_tf32_kernel(const float* __restrict__ A, const float* __restrict__ B,
                 float* __restrict__ C, int M, int N, int K)
{
    extern __shared__ __align__(16) char smem[];
    const uint32_t su = smem_to_u32(smem);

    const int tid    = threadIdx.x;
    const int lane   = tid & 31;
    const int wid    = tid >> 5;
    const int warp_m = wid >> 2;
    const int warp_n = wid & 3;
    const int m0 = blockIdx.y * 128;
    const int n0 = blockIdx.x * 128;

    const int nchunks = K / 32;   /* 32 */

    /* cp.async: A+B = 2 x 128 rows x 8 x 16B = 2048 xfers, 8/thread */
    auto issue_stage = [&](int s, int i) {
        const uint32_t sb = su + s * TSTG;
        #pragma unroll
        for (int t = 0; t < 4; t++) {
            const int idx = tid + t * 256;          /* 0..1023 */
            const int row = idx >> 3, c = idx & 7;
            const uint32_t so = (uint32_t)row * TPAD + c * 16;
            const size_t ga = (size_t)(m0 + row) * K + i * 32 + c * 4;
            const size_t gb = (size_t)(n0 + row) * K + i * 32 + c * 4;
            CP_ASYNC16(sb + so, A + ga);
            CP_ASYNC16(sb + TTILE + so, B + gb);
        }
        CP_COMMIT();
    };

    issue_stage(0, 0);

    const int arow = warp_m * 64 + (lane >> 2);
    const int brow = warp_n * 32 + (lane >> 2);
    const int coff = (lane & 3) * 4;

    float acc[4][4][4] = {};

    for (int i = 0; i < nchunks; i++) {
        const int s = i & 1;
        if (i + 1 < nchunks) { issue_stage(s ^ 1, i + 1); CP_WAIT1(); }
        else                 { CP_WAIT0(); }
        __syncthreads();

        const char* sa  = smem + s * TSTG;
        const char* sbb = smem + s * TSTG + TTILE;

        #pragma unroll
        for (int ks = 0; ks < 4; ks++) {
            uint32_t af[4][4];
            #pragma unroll
            for (int mt = 0; mt < 4; mt++) {
                const char* ab = sa + (arow + mt * 16) * TPAD + coff + ks * 32;
                af[mt][0] = *(const uint32_t*)(ab);
                af[mt][1] = *(const uint32_t*)(ab + 8 * TPAD);
                af[mt][2] = *(const uint32_t*)(ab + 16);
                af[mt][3] = *(const uint32_t*)(ab + 8 * TPAD + 16);
            }
            uint32_t bf[4][2];
            #pragma unroll
            for (int nt = 0; nt < 4; nt++) {
                const char* bb = sbb + (brow + nt * 8) * TPAD + coff + ks * 32;
                bf[nt][0] = *(const uint32_t*)(bb);
                bf[nt][1] = *(const uint32_t*)(bb + 16);
            }
            #pragma unroll
            for (int mt = 0; mt < 4; mt++)
                #pragma unroll
                for (int nt = 0; nt < 4; nt++)
                    MMA_TF32(acc[mt][nt], af[mt], bf[nt]);
        }
        __syncthreads();
    }

    #pragma unroll
    for (int mt = 0; mt < 4; mt++) {
        const int m = m0 + warp_m * 64 + mt * 16 + (lane >> 2);
        #pragma unroll
        for (int nt = 0; nt < 4; nt++) {
            const int n = n0 + warp_n * 32 + nt * 8 + (lane & 3) * 2;
            *(float2*)(C + (size_t)m * N + n) =
                make_float2(acc[mt][nt][0], acc[mt][nt][1]);
            *(float2*)(C + (size_t)(m + 8) * N + n) =
                make_float2(acc[mt][nt][2], acc[mt][nt][3]);
        }
    }
}

/* ============================================================
 * Fused RoPE for Q and K (sincos once per position) -> bf16 hi/lo.
 * ============================================================ */
__global__ void __launch_bounds__(256)
rope2_kernel(const float* __restrict__ q, const float* __restrict__ k,
             __nv_bfloat16* __restrict__ qh, __nv_bfloat16* __restrict__ ql,
             __nv_bfloat16* __restrict__ kh, __nv_bfloat16* __restrict__ kl)
{
    __shared__ float invf[32];
    const int tid = threadIdx.x;
    if (tid < 32) invf[tid] = (float)pow(10000.0, -(double)tid / 32.0);
    __syncthreads();

    const int bs   = blockIdx.x * 8 + (tid >> 5);
    const int lane = tid & 31;
    const int pos  = bs & (SEQ - 1);

    float s1, c1, s2, c2;
    sincosf((float)pos * invf[(2 * lane) & 31],     &s1, &c1);
    sincosf((float)pos * invf[(2 * lane + 1) & 31], &s2, &c2);

    const size_t base = (size_t)bs * D_MODEL;
    #pragma unroll
    for (int h = 0; h < N_HEADS; h++) {
        const size_t ro = base + h * 64;
        {
            float x0 = q[ro + 2 * lane], x1 = q[ro + 2 * lane + 1];
            float y0 = (x0 * c1 - x1 * s1) * 0.125f;
            float y1 = (x0 * s2 + x1 * c2) * 0.125f;
            __nv_bfloat16 h0 = __float2bfloat16_rn(y0);
            __nv_bfloat16 h1 = __float2bfloat16_rn(y1);
            qh[ro + lane]      = h0;
            ql[ro + lane]      = __float2bfloat16_rn(y0 - __bfloat162float(h0));
            qh[ro + 32 + lane] = h1;
            ql[ro + 32 + lane] = __float2bfloat16_rn(y1 - __bfloat162float(h1));
        }
        {
            float x0 = k[ro + 2 * lane], x1 = k[ro + 2 * lane + 1];
            float y0 = x0 * c1 - x1 * s1;
            float y1 = x0 * s2 + x1 * c2;
            __nv_bfloat16 h0 = __float2bfloat16_rn(y0);
            __nv_bfloat16 h1 = __float2bfloat16_rn(y1);
            kh[ro + lane]      = h0;
            kl[ro + lane]      = __float2bfloat16_rn(y0 - __bfloat162float(h0));
            kh[ro + 32 + lane] = h1;
            kl[ro + 32 + lane] = __float2bfloat16_rn(y1 - __bfloat162float(h1));
        }
    }
}

/* ============================================================
 * V transpose + split: g_v -> vt [bh][d][S] bf16 hi/lo.
 * ============================================================ */
__global__ void __launch_bounds__(256)
vtrans_kernel(const float* __restrict__ v,
              __nv_bfloat16* __restrict__ vth, __nv_bfloat16* __restrict__ vtl)
{
    __shared__ float t[64][65];
    const int sblk = blockIdx.x;
    const int bh   = blockIdx.y;
    const int tid  = threadIdx.x;

    {
        const int row = tid >> 2;
        const int c0  = (tid & 3) * 16;
        const size_t gaddr = ((size_t)(bh >> 4) * SEQ + sblk * 64 + row) * D_MODEL
                           + (bh & 15) * 64 + c0;
        #pragma unroll
        for (int f = 0; f < 4; f++) {
            float4 vv = *(const float4*)(v + gaddr + f * 4);
            t[row][c0 + f * 4 + 0] = vv.x; t[row][c0 + f * 4 + 1] = vv.y;
            t[row][c0 + f * 4 + 2] = vv.z; t[row][c0 + f * 4 + 3] = vv.w;
        }
    }
    __syncthreads();

    const int d  = tid >> 2;
    const int k0 = (tid & 3) * 16;
    __nv_bfloat16 hv[16], lv[16];
    #pragma unroll
    for (int kk = 0; kk < 16; kk++) {
        float x = t[k0 + kk][d];
        hv[kk] = __float2bfloat16_rn(x);
        lv[kk] = __float2bfloat16_rn(x - __bfloat162float(hv[kk]));
    }
    const size_t dst = ((size_t)bh * 64 + d) * SEQ + sblk * 64 + k0;
    *(uint4*)(vth + dst)     = *(uint4*)(hv);
    *(uint4*)(vth + dst + 8) = *(uint4*)(hv + 8);
    *(uint4*)(vtl + dst)     = *(uint4*)(lv);
    *(uint4*)(vtl + dst + 8) = *(uint4*)(lv + 8);
}

/* ============================================================
 * Flash attention, causal, split-bf16 mma.sync, cp.async pipeline,
 * per-warp masked-subtile skipping. Output: tf32-rounded fp32.
 * ============================================================ */
#define AQP 144
#define AQTILE (128 * AQP)
#define AKTILE (64 * AQP)
#define ASTAGE (4 * AKTILE)
#define ATTN_SMEM (2 * AQTILE + 2 * ASTAGE)  /* 110592 */

__global__ void __launch_bounds__(256)
attn_mma_kernel(const __nv_bfloat16* __restrict__ qh, const __nv_bfloat16* __restrict__ ql,
                const __nv_bfloat16* __restrict__ kh, const __nv_bfloat16* __restrict__ kl,
                const __nv_bfloat16* __restrict__ vth, const __nv_bfloat16* __restrict__ vtl,
                float* __restrict__ o)
{
    extern __shared__ __align__(16) char sm[];
    const uint32_t su = smem_to_u32(sm);

    const int qb   = gridDim.x - 1 - blockIdx.x;
    const int bh   = blockIdx.y;
    const int tid  = threadIdx.x;
    const int lane = tid & 31;
    const int wid  = tid >> 5;

    const int b = bh >> 4, h = bh & 15;
    const size_t qkrow0 = ((size_t)b * SEQ) * D_MODEL + (size_t)h * 64;
    const size_t vtrow0 = ((size_t)bh * 64) * SEQ;

    {
        const int lrow = tid >> 1, lhalf = tid & 1;
        const uint32_t sts = (uint32_t)lrow * AQP + lhalf * 64;
        const size_t g = qkrow0 + (size_t)(qb * 128 + lrow) * D_MODEL + lhalf * 32;
        const uint4* sh = (const uint4*)(qh + g);
        const uint4* sl = (const uint4*)(ql + g);
        uint4* dh = (uint4*)(sm + sts);
        uint4* dl = (uint4*)(sm + AQTILE + sts);
        #pragma unroll
        for (int f = 0; f < 4; f++) { dh[f] = sh[f]; dl[f] = sl[f]; }
    }

    const int nkb = 2 * qb + 2;

    auto issue_stage = [&](int s, int kb) {
        const uint32_t sb = su + 2 * AQTILE + s * ASTAGE;
        #pragma unroll
        for (int i = 0; i < 2; i++) {
            const int idx = tid + i * 256;
            const int row = idx >> 3, c = idx & 7;
            const uint32_t so = (uint32_t)row * AQP + c * 16;
            const size_t gk = qkrow0 + (size_t)(kb * 64 + row) * D_MODEL + c * 8;
            const size_t gv = vtrow0 + (size_t)row * SEQ + kb * 64 + c * 8;
            CP_ASYNC16(sb + 0 * AKTILE + so, kh + gk);
            CP_ASYNC16(sb + 1 * AKTILE + so, kl + gk);
            CP_ASYNC16(sb + 2 * AKTILE + so, vth + gv);
            CP_ASYNC16(sb + 3 * AKTILE + so, vtl + gv);
        }
        CP_COMMIT();
    };

    issue_stage(0, 0);

    const uint32_t a_ld = su + (uint32_t)(wid * 16 + (lane & 15)) * AQP + (lane >> 4) * 16;
    const uint32_t t_ld = su + 2 * AQTILE + (uint32_t)(lane & 15) * AQP + (lane >> 4) * 16;

    float acc[8][4] = {};
    float mo1 = -1e30f, mo2 = -1e30f, l1 = 0.0f, l2 = 0.0f;
    const int q1g = qb * 128 + wid * 16 + (lane >> 2);
    const int warp_qmax = qb * 128 + wid * 16 + 15;

    for (int kb = 0; kb < nkb; kb++) {
        const int s = kb & 1;
        if (kb + 1 < nkb) { issue_stage(s ^ 1, kb + 1); CP_WAIT1(); }
        else              { CP_WAIT0(); }
        __syncthreads();

        const bool tile_active = (kb * 64 <= warp_qmax);   /* warp-uniform */

        if (tile_active) {
            const uint32_t kb_ld = t_ld + s * ASTAGE;

            float sc[8][4] = {};
            #pragma unroll
            for (int ks = 0; ks < 4; ks++) {
                uint32_t ah[4], al[4];
                LDSM_X4(ah[0], ah[1], ah[2], ah[3], a_ld + ks * 32 + 0 * AQTILE);
                LDSM_X4(al[0], al[1], al[2], al[3], a_ld + ks * 32 + 1 * AQTILE);
                #pragma unroll
                for (int nb = 0; nb < 4; nb++) {
                    if (kb * 64 + nb * 16 > warp_qmax) continue;   /* fully masked */
                    uint32_t r0, r1, r2, r3, q0, q1, q2, q3;
                    LDSM_X4(r0, r1, r2, r3, kb_ld + nb * 16 * AQP + ks * 32 + 0 * AKTILE);
                    LDSM_X4(q0, q1, q2, q3, kb_ld + nb * 16 * AQP + ks * 32 + 1 * AKTILE);
                    uint32_t be[2] = {r0, r2}, bo[2] = {r1, r3};
                    uint32_t le[2] = {q0, q2}, lo_[2] = {q1, q3};
                    MMA_BF16(sc[2 * nb],     ah, be); MMA_BF16(sc[2 * nb],     ah, le); MMA_BF16(sc[2 * nb],     al, be);
                    MMA_BF16(sc[2 * nb + 1], ah, bo); MMA_BF16(sc[2 * nb + 1], ah, lo_); MMA_BF16(sc[2 * nb + 1], al, bo);
                }
            }

            if (kb * 64 + 63 > qb * 128 + wid * 16) {
                #pragma unroll
                for (int j = 0; j < 8; j++) {
                    const int c = kb * 64 + j * 8 + (lane & 3) * 2;
                    if (c     > q1g)     sc[j][0] = -1e30f;
                    if (c + 1 > q1g)     sc[j][1] = -1e30f;
                    if (c     > q1g + 8) sc[j][2] = -1e30f;
                    if (c + 1 > q1g + 8) sc[j][3] = -1e30f;
                }
            }

            float m1 = -1e30f, m2 = -1e30f;
            #pragma unroll
            for (int j = 0; j < 8; j++) {
                m1 = fmaxf(m1, fmaxf(sc[j][0], sc[j][1]));
                m2 = fmaxf(m2, fmaxf(sc[j][2], sc[j][3]));
            }
            m1 = fmaxf(m1, __shfl_xor_sync(0xffffffffu, m1, 1));
            m1 = fmaxf(m1, __shfl_xor_sync(0xffffffffu, m1, 2));
            m2 = fmaxf(m2, __shfl_xor_sync(0xffffffffu, m2, 1));
            m2 = fmaxf(m2, __shfl_xor_sync(0xffffffffu, m2, 2));
            const float mn1 = fmaxf(mo1, m1), mn2 = fmaxf(mo2, m2);
            const float sc1 = __expf(mo1 - mn1), sc2 = __expf(mo2 - mn2);
            float sum1 = 0.0f, sum2 = 0.0f;
            #pragma unroll
            for (int j = 0; j < 8; j++) {
                sc[j][0] = __expf(sc[j][0] - mn1); sum1 += sc[j][0];
                sc[j][1] = __expf(sc[j][1] - mn1); sum1 += sc[j][1];
                sc[j][2] = __expf(sc[j][2] - mn2); sum2 += sc[j][2];
                sc[j][3] = __expf(sc[j][3] - mn2); sum2 += sc[j][3];
            }
            sum1 += __shfl_xor_sync(0xffffffffu, sum1, 1);
            sum1 += __shfl_xor_sync(0xffffffffu, sum1, 2);
            sum2 += __shfl_xor_sync(0xffffffffu, sum2, 1);
            sum2 += __shfl_xor_sync(0xffffffffu, sum2, 2);
            l1 = l1 * sc1 + sum1; l2 = l2 * sc2 + sum2;
            mo1 = mn1; mo2 = mn2;
            #pragma unroll
            for (int j = 0; j < 8; j++) {
                acc[j][0] *= sc1; acc[j][1] *= sc1;
                acc[j][2] *= sc2; acc[j][3] *= sc2;
            }

            #pragma unroll
            for (int ks = 0; ks < 4; ks++) {
                if (kb * 64 + ks * 16 > warp_qmax) continue;   /* P all-zero */
                uint32_t ph[4], pl[4];
                #pragma unroll
                for (int t2 = 0; t2 < 2; t2++) {
                    const int j = 2 * ks + t2;
                    __nv_bfloat16 h0 = __float2bfloat16_rn(sc[j][0]);
                    __nv_bfloat16 h1 = __float2bfloat16_rn(sc[j][1]);
                    __nv_bfloat16 h2 = __float2bfloat16_rn(sc[j][2]);
                    __nv_bfloat16 h3 = __float2bfloat16_rn(sc[j][3]);
                    ph[2 * t2]     = pk_bf16x2(h0, h1);
                    ph[2 * t2 + 1] = pk_bf16x2(h2, h3);
                    pl[2 * t2]     = pk_bf16x2(
                        __float2bfloat16_rn(sc[j][0] - __bfloat162float(h0)),
                        __float2bfloat16_rn(sc[j][1] - __bfloat162float(h1)));
                    pl[2 * t2 + 1] = pk_bf16x2(
                        __float2bfloat16_rn(sc[j][2] - __bfloat162float(h2)),
                        __float2bfloat16_rn(sc[j][3] - __bfloat162float(h3)));
                }
                #pragma unroll
                for (int nb = 0; nb < 4; nb++) {
                    uint32_t r0, r1, r2, r3, q0, q1, q2, q3;
                    LDSM_X4(r0, r1, r2, r3, kb_ld + nb * 16 * AQP + ks * 32 + 2 * AKTILE);
                    LDSM_X4(q0, q1, q2, q3, kb_ld + nb * 16 * AQP + ks * 32 + 3 * AKTILE);
                    uint32_t be[2] = {r0, r2}, bo[2] = {r1, r3};
                    uint32_t le[2] = {q0, q2}, lo_[2] = {q1, q3};
                    MMA_BF16(acc[2 * nb],     ph, be); MMA_BF16(acc[2 * nb],     ph, le); MMA_BF16(acc[2 * nb],     pl, be);
                    MMA_BF16(acc[2 * nb + 1], ph, bo); MMA_BF16(acc[2 * nb + 1], ph, lo_); MMA_BF16(acc[2 * nb + 1], pl, bo);
                }
            }
        }
        __syncthreads();
    }

    /* epilogue: normalize, tf32-round, store fp32 */
    const float i1 = 1.0f / l1, i2 = 1.0f / l2;
    const size_t r1a = qkrow0 + (size_t)(qb * 128 + wid * 16 + (lane >> 2)) * D_MODEL;
    const size_t r2a = r1a + 8 * D_MODEL;
    #pragma unroll
    for (int j = 0; j < 8; j++) {
        const int c = j * 8 + (lane & 3) * 2;
        *(float2*)(o + r1a + c) = make_float2(tf32r(acc[j][0] * i1), tf32r(acc[j][1] * i1));
        *(float2*)(o + r2a + c) = make_float2(tf32r(acc[j][2] * i2), tf32r(acc[j][3] * i2));
    }
}

/* ============================================================ */
extern "C" void kernel_launch(void* const* d_in, const int* in_sizes, int n_in,
                              void* d_out, int out_size)
{
    const float* x  = (const float*)d_in[0];
    const float* W[4] = { (const float*)d_in[1], (const float*)d_in[2],
                          (const float*)d_in[3], (const float*)d_in[4] };
    float* out = (float*)d_out;

    float *qp, *kp, *vp, *xr, *wr;
    __nv_bfloat16 *qhp, *qlp, *khp, *klp, *vthp, *vtlp;
    cudaGetSymbolAddress((void**)&qp, g_q);
    cudaGetSymbolAddress((void**)&kp, g_k);
    cudaGetSymbolAddress((void**)&vp, g_v);
    cudaGetSymbolAddress((void**)&xr, g_xr);
    cudaGetSymbolAddress((void**)&wr, g_wr);
    cudaGetSymbolAddress((void**)&qhp, g_qh);
    cudaGetSymbolAddress((void**)&qlp, g_ql);
    cudaGetSymbolAddress((void**)&khp, g_kh);
    cudaGetSymbolAddress((void**)&klp, g_kl);
    cudaGetSymbolAddress((void**)&vthp, g_vth);
    cudaGetSymbolAddress((void**)&vtlp, g_vtl);

    static bool attr_done = false;
    if (!attr_done) {
        cudaFuncSetAttribute(gemm_tf32_kernel,
                             cudaFuncAttributeMaxDynamicSharedMemorySize, GEMM_SMEM);
        cudaFuncSetAttribute(attn_mma_kernel,
                             cudaFuncAttributeMaxDynamicSharedMemorySize, ATTN_SMEM);
        attr_done = true;
    }

    const size_t WSZ = (size_t)D_MODEL * D_MODEL;

    /* tf32-round x and weights */
    round_kernel<<<M_TOT * D_MODEL / 1024, 256>>>(x, xr);
    for (int i = 0; i < 4; i++)
        round_kernel<<<WSZ / 1024, 256>>>(W[i], wr + i * WSZ);

    const dim3 gg(D_MODEL / 128, M_TOT / 128);   /* (8, 32) */

    gemm_tf32_kernel<<<gg, 256, GEMM_SMEM>>>(xr, wr + 0 * WSZ, qp, M_TOT, D_MODEL, D_MODEL);
    gemm_tf32_kernel<<<gg, 256, GEMM_SMEM>>>(xr, wr + 1 * WSZ, kp, M_TOT, D_MODEL, D_MODEL);
    gemm_tf32_kernel<<<gg, 256, GEMM_SMEM>>>(xr, wr + 2 * WSZ, vp, M_TOT, D_MODEL, D_MODEL);

    rope2_kernel<<<M_TOT / 8, 256>>>(qp, kp, qhp, qlp, khp, klp);
    vtrans_kernel<<<dim3(SEQ / 64, BATCH * N_HEADS), 256>>>(vp, vthp, vtlp);

    /* attention output (tf32-rounded fp32) overwrites g_q */
    attn_mma_kernel<<<dim3(SEQ / 128, BATCH * N_HEADS), 256, ATTN_SMEM>>>(
        qhp, qlp, khp, klp, vthp, vtlp, qp);

    gemm_tf32_kernel<<<gg, 256, GEMM_SMEM>>>(qp, wr + 3 * WSZ, out, M_TOT, D_MODEL, D_MODEL);
}

// round 10
// speedup vs baseline: 4.0616x; 1.1192x over previous
#include <cuda_runtime.h>
#include <cuda_bf16.h>
#include <math.h>
#include <stdint.h>

#define D_MODEL 1024
#define N_HEADS 16
#define HEAD_DIM 64
#define BATCH 2
#define SEQ 2048
#define M_TOT (BATCH * SEQ)   /* 4096 */

/* ---- scratch (allocation-free: __device__ globals) ---- */
__device__ float g_q[(size_t)M_TOT * D_MODEL];   /* q, later reused as O */
__device__ float g_k[(size_t)M_TOT * D_MODEL];
__device__ float g_v[(size_t)M_TOT * D_MODEL];
__device__ float g_xr[(size_t)M_TOT * D_MODEL];          /* tf32-rounded x */
__device__ float g_wr[4][(size_t)D_MODEL * D_MODEL];     /* tf32-rounded W */
__device__ __nv_bfloat16 g_qh[(size_t)M_TOT * D_MODEL];
__device__ __nv_bfloat16 g_ql[(size_t)M_TOT * D_MODEL];
__device__ __nv_bfloat16 g_kh[(size_t)M_TOT * D_MODEL];
__device__ __nv_bfloat16 g_kl[(size_t)M_TOT * D_MODEL];
__device__ __nv_bfloat16 g_vth[(size_t)M_TOT * D_MODEL]; /* [bh][d][S] */
__device__ __nv_bfloat16 g_vtl[(size_t)M_TOT * D_MODEL];

__device__ __forceinline__ uint32_t smem_to_u32(const void* p) {
    uint32_t a;
    asm("{ .reg .u64 t; cvta.to.shared.u64 t, %1; cvt.u32.u64 %0, t; }" : "=r"(a) : "l"(p));
    return a;
}

#define LDSM_X4(r0, r1, r2, r3, addr) \
    asm volatile("ldmatrix.sync.aligned.m8n8.x4.shared.b16 {%0,%1,%2,%3}, [%4];" \
                 : "=r"(r0), "=r"(r1), "=r"(r2), "=r"(r3) : "r"(addr))

#define MMA_BF16(c, a, b) \
    asm volatile("mma.sync.aligned.m16n8k16.row.col.f32.bf16.bf16.f32 " \
                 "{%0,%1,%2,%3},{%4,%5,%6,%7},{%8,%9},{%0,%1,%2,%3};" \
                 : "+f"((c)[0]), "+f"((c)[1]), "+f"((c)[2]), "+f"((c)[3]) \
                 : "r"((a)[0]), "r"((a)[1]), "r"((a)[2]), "r"((a)[3]), \
                   "r"((b)[0]), "r"((b)[1]))

#define MMA_TF32(c, a, b) \
    asm volatile("mma.sync.aligned.m16n8k8.row.col.f32.tf32.tf32.f32 " \
                 "{%0,%1,%2,%3},{%4,%5,%6,%7},{%8,%9},{%0,%1,%2,%3};" \
                 : "+f"((c)[0]), "+f"((c)[1]), "+f"((c)[2]), "+f"((c)[3]) \
                 : "r"((a)[0]), "r"((a)[1]), "r"((a)[2]), "r"((a)[3]), \
                   "r"((b)[0]), "r"((b)[1]))

#define CP_ASYNC16(saddr, gptr) \
    asm volatile("cp.async.cg.shared.global [%0], [%1], 16;" \
                 :: "r"(saddr), "l"(gptr) : "memory")
#define CP_COMMIT() asm volatile("cp.async.commit_group;" ::: "memory")
#define CP_WAIT0()  asm volatile("cp.async.wait_group 0;" ::: "memory")
#define CP_WAIT1()  asm volatile("cp.async.wait_group 1;" ::: "memory")

__device__ __forceinline__ uint32_t pk_bf16x2(__nv_bfloat16 a, __nv_bfloat16 b) {
    return (uint32_t)__bfloat16_as_ushort(a) | ((uint32_t)__bfloat16_as_ushort(b) << 16);
}
__device__ __forceinline__ float tf32r(float x) {
    uint32_t r;
    asm("cvt.rna.tf32.f32 %0, %1;" : "=r"(r) : "f"(x));
    return __uint_as_float(r);
}

/* ============================================================
 * Merged fp32 -> tf32 rounding for x + all 4 weights (1 launch).
 * blocks 0..4095: x;  4096..8191: W[(b-4096)>>10]
 * ============================================================ */
__global__ void __launch_bounds__(256)
round_all_kernel(const float* __restrict__ x,
                 const float* __restrict__ w0, const float* __restrict__ w1,
                 const float* __restrict__ w2, const float* __restrict__ w3,
                 float* __restrict__ xr, float* __restrict__ wr)
{
    const int b = blockIdx.x;
    const float* src;
    float* dst;
    int lb;
    if (b < 4096) { src = x; dst = xr; lb = b; }
    else {
        const int r = b - 4096;
        const int w = r >> 10;
        src = (w == 0) ? w0 : (w == 1) ? w1 : (w == 2) ? w2 : w3;
        dst = wr + (size_t)w * D_MODEL * D_MODEL;
        lb = r & 1023;
    }
    const size_t i = ((size_t)lb * 256 + threadIdx.x) * 4;
    float4 v = *(const float4*)(src + i);
    v.x = tf32r(v.x); v.y = tf32r(v.y); v.z = tf32r(v.z); v.w = tf32r(v.w);
    *(float4*)(dst + i) = v;
}

/* ============================================================
 * tf32 single-pass GEMM (at tf32 mma roofline; unchanged).
 * ============================================================ */
#define TPAD 144
#define TTILE (128 * TPAD)
#define TSTG (2 * TTILE)
#define GEMM_SMEM (2 * TSTG)  /* 73728 */

__global__ void __launch_bounds__(256, 2)
gemm_tf32_kernel(const float* __restrict__ A, const float* __restrict__ B,
                 float* __restrict__ C, int M, int N, int K)
{
    extern __shared__ __align__(16) char smem[];
    const uint32_t su = smem_to_u32(smem);

    const int tid    = threadIdx.x;
    const int lane   = tid & 31;
    const int wid    = tid >> 5;
    const int warp_m = wid >> 2;
    const int warp_n = wid & 3;
    const int m0 = blockIdx.y * 128;
    const int n0 = blockIdx.x * 128;

    const int nchunks = K / 32;

    auto issue_stage = [&](int s, int i) {
        const uint32_t sb = su + s * TSTG;
        #pragma unroll
        for (int t = 0; t < 4; t++) {
            const int idx = tid + t * 256;
            const int row = idx >> 3, c = idx & 7;
            const uint32_t so = (uint32_t)row * TPAD + c * 16;
            const size_t ga = (size_t)(m0 + row) * K + i * 32 + c * 4;
            const size_t gb = (size_t)(n0 + row) * K + i * 32 + c * 4;
            CP_ASYNC16(sb + so, A + ga);
            CP_ASYNC16(sb + TTILE + so, B + gb);
        }
        CP_COMMIT();
    };

    issue_stage(0, 0);

    const int arow = warp_m * 64 + (lane >> 2);
    const int brow = warp_n * 32 + (lane >> 2);
    const int coff = (lane & 3) * 4;

    float acc[4][4][4] = {};

    for (int i = 0; i < nchunks; i++) {
        const int s = i & 1;
        if (i + 1 < nchunks) { issue_stage(s ^ 1, i + 1); CP_WAIT1(); }
        else                 { CP_WAIT0(); }
        __syncthreads();

        const char* sa  = smem + s * TSTG;
        const char* sbb = smem + s * TSTG + TTILE;

        #pragma unroll
        for (int ks = 0; ks < 4; ks++) {
            uint32_t af[4][4];
            #pragma unroll
            for (int mt = 0; mt < 4; mt++) {
                const char* ab = sa + (arow + mt * 16) * TPAD + coff + ks * 32;
                af[mt][0] = *(const uint32_t*)(ab);
                af[mt][1] = *(const uint32_t*)(ab + 8 * TPAD);
                af[mt][2] = *(const uint32_t*)(ab + 16);
                af[mt][3] = *(const uint32_t*)(ab + 8 * TPAD + 16);
            }
            uint32_t bf[4][2];
            #pragma unroll
            for (int nt = 0; nt < 4; nt++) {
                const char* bb = sbb + (brow + nt * 8) * TPAD + coff + ks * 32;
                bf[nt][0] = *(const uint32_t*)(bb);
                bf[nt][1] = *(const uint32_t*)(bb + 16);
            }
            #pragma unroll
            for (int mt = 0; mt < 4; mt++)
                #pragma unroll
                for (int nt = 0; nt < 4; nt++)
                    MMA_TF32(acc[mt][nt], af[mt], bf[nt]);
        }
        __syncthreads();
    }

    #pragma unroll
    for (int mt = 0; mt < 4; mt++) {
        const int m = m0 + warp_m * 64 + mt * 16 + (lane >> 2);
        #pragma unroll
        for (int nt = 0; nt < 4; nt++) {
            const int n = n0 + warp_n * 32 + nt * 8 + (lane & 3) * 2;
            *(float2*)(C + (size_t)m * N + n) =
                make_float2(acc[mt][nt][0], acc[mt][nt][1]);
            *(float2*)(C + (size_t)(m + 8) * N + n) =
                make_float2(acc[mt][nt][2], acc[mt][nt][3]);
        }
    }
}

/* ============================================================
 * Fused RoPE for Q and K -> bf16 hi/lo (unchanged).
 * ============================================================ */
__global__ void __launch_bounds__(256)
rope2_kernel(const float* __restrict__ q, const float* __restrict__ k,
             __nv_bfloat16* __restrict__ qh, __nv_bfloat16* __restrict__ ql,
             __nv_bfloat16* __restrict__ kh, __nv_bfloat16* __restrict__ kl)
{
    __shared__ float invf[32];
    const int tid = threadIdx.x;
    if (tid < 32) invf[tid] = (float)pow(10000.0, -(double)tid / 32.0);
    __syncthreads();

    const int bs   = blockIdx.x * 8 + (tid >> 5);
    const int lane = tid & 31;
    const int pos  = bs & (SEQ - 1);

    float s1, c1, s2, c2;
    sincosf((float)pos * invf[(2 * lane) & 31],     &s1, &c1);
    sincosf((float)pos * invf[(2 * lane + 1) & 31], &s2, &c2);

    const size_t base = (size_t)bs * D_MODEL;
    #pragma unroll
    for (int h = 0; h < N_HEADS; h++) {
        const size_t ro = base + h * 64;
        {
            float x0 = q[ro + 2 * lane], x1 = q[ro + 2 * lane + 1];
            float y0 = (x0 * c1 - x1 * s1) * 0.125f;
            float y1 = (x0 * s2 + x1 * c2) * 0.125f;
            __nv_bfloat16 h0 = __float2bfloat16_rn(y0);
            __nv_bfloat16 h1 = __float2bfloat16_rn(y1);
            qh[ro + lane]      = h0;
            ql[ro + lane]      = __float2bfloat16_rn(y0 - __bfloat162float(h0));
            qh[ro + 32 + lane] = h1;
            ql[ro + 32 + lane] = __float2bfloat16_rn(y1 - __bfloat162float(h1));
        }
        {
            float x0 = k[ro + 2 * lane], x1 = k[ro + 2 * lane + 1];
            float y0 = x0 * c1 - x1 * s1;
            float y1 = x0 * s2 + x1 * c2;
            __nv_bfloat16 h0 = __float2bfloat16_rn(y0);
            __nv_bfloat16 h1 = __float2bfloat16_rn(y1);
            kh[ro + lane]      = h0;
            kl[ro + lane]      = __float2bfloat16_rn(y0 - __bfloat162float(h0));
            kh[ro + 32 + lane] = h1;
            kl[ro + 32 + lane] = __float2bfloat16_rn(y1 - __bfloat162float(h1));
        }
    }
}

/* ============================================================
 * V transpose + split (unchanged).
 * ============================================================ */
__global__ void __launch_bounds__(256)
vtrans_kernel(const float* __restrict__ v,
              __nv_bfloat16* __restrict__ vth, __nv_bfloat16* __restrict__ vtl)
{
    __shared__ float t[64][65];
    const int sblk = blockIdx.x;
    const int bh   = blockIdx.y;
    const int tid  = threadIdx.x;

    {
        const int row = tid >> 2;
        const int c0  = (tid & 3) * 16;
        const size_t gaddr = ((size_t)(bh >> 4) * SEQ + sblk * 64 + row) * D_MODEL
                           + (bh & 15) * 64 + c0;
        #pragma unroll
        for (int f = 0; f < 4; f++) {
            float4 vv = *(const float4*)(v + gaddr + f * 4);
            t[row][c0 + f * 4 + 0] = vv.x; t[row][c0 + f * 4 + 1] = vv.y;
            t[row][c0 + f * 4 + 2] = vv.z; t[row][c0 + f * 4 + 3] = vv.w;
        }
    }
    __syncthreads();

    const int d  = tid >> 2;
    const int k0 = (tid & 3) * 16;
    __nv_bfloat16 hv[16], lv[16];
    #pragma unroll
    for (int kk = 0; kk < 16; kk++) {
        float x = t[k0 + kk][d];
        hv[kk] = __float2bfloat16_rn(x);
        lv[kk] = __float2bfloat16_rn(x - __bfloat162float(hv[kk]));
    }
    const size_t dst = ((size_t)bh * 64 + d) * SEQ + sblk * 64 + k0;
    *(uint4*)(vth + dst)     = *(uint4*)(hv);
    *(uint4*)(vth + dst + 8) = *(uint4*)(hv + 8);
    *(uint4*)(vtl + dst)     = *(uint4*)(lv);
    *(uint4*)(vtl + dst + 8) = *(uint4*)(lv + 8);
}

/* ============================================================
 * Flash attention, causal, split-bf16 mma.sync, cp.async pipeline.
 * qb-PAIRED: each CTA processes q-blocks {x, 15-x} -> equal work
 * (34 key-tiles per CTA). Grid (8, 32); 2 CTAs/SM resident.
 * ============================================================ */
#define AQP 144
#define AQTILE (128 * AQP)
#define AKTILE (64 * AQP)
#define ASTAGE (4 * AKTILE)
#define ATTN_SMEM (2 * AQTILE + 2 * ASTAGE)  /* 110592 */
#define NQB (SEQ / 128)                      /* 16 */

__global__ void __launch_bounds__(256, 2)
attn_mma_kernel(const __nv_bfloat16* __restrict__ qh, const __nv_bfloat16* __restrict__ ql,
                const __nv_bfloat16* __restrict__ kh, const __nv_bfloat16* __restrict__ kl,
                const __nv_bfloat16* __restrict__ vth, const __nv_bfloat16* __restrict__ vtl,
                float* __restrict__ o)
{
    extern __shared__ __align__(16) char sm[];
    const uint32_t su = smem_to_u32(sm);

    const int bh   = blockIdx.y;
    const int tid  = threadIdx.x;
    const int lane = tid & 31;
    const int wid  = tid >> 5;

    const int b = bh >> 4, h = bh & 15;
    const size_t qkrow0 = ((size_t)b * SEQ) * D_MODEL + (size_t)h * 64;
    const size_t vtrow0 = ((size_t)bh * 64) * SEQ;

    const uint32_t a_ld = su + (uint32_t)(wid * 16 + (lane & 15)) * AQP + (lane >> 4) * 16;
    const uint32_t t_ld = su + 2 * AQTILE + (uint32_t)(lane & 15) * AQP + (lane >> 4) * 16;

    auto issue_stage = [&](int s, int kb) {
        const uint32_t sb = su + 2 * AQTILE + s * ASTAGE;
        #pragma unroll
        for (int i = 0; i < 2; i++) {
            const int idx = tid + i * 256;
            const int row = idx >> 3, c = idx & 7;
            const uint32_t so = (uint32_t)row * AQP + c * 16;
            const size_t gk = qkrow0 + (size_t)(kb * 64 + row) * D_MODEL + c * 8;
            const size_t gv = vtrow0 + (size_t)row * SEQ + kb * 64 + c * 8;
            CP_ASYNC16(sb + 0 * AKTILE + so, kh + gk);
            CP_ASYNC16(sb + 1 * AKTILE + so, kl + gk);
            CP_ASYNC16(sb + 2 * AKTILE + so, vth + gv);
            CP_ASYNC16(sb + 3 * AKTILE + so, vtl + gv);
        }
        CP_COMMIT();
    };

    #pragma unroll 1
    for (int qi = 0; qi < 2; qi++) {
        const int qb = (qi == 0) ? blockIdx.x : (NQB - 1 - blockIdx.x);

        /* load Q tile (safe: all smem reads of prior iter end at its last barrier) */
        {
            const int lrow = tid >> 1, lhalf = tid & 1;
            const uint32_t sts = (uint32_t)lrow * AQP + lhalf * 64;
            const size_t g = qkrow0 + (size_t)(qb * 128 + lrow) * D_MODEL + lhalf * 32;
            const uint4* sh = (const uint4*)(qh + g);
            const uint4* sl = (const uint4*)(ql + g);
            uint4* dh = (uint4*)(sm + sts);
            uint4* dl = (uint4*)(sm + AQTILE + sts);
            #pragma unroll
            for (int f = 0; f < 4; f++) { dh[f] = sh[f]; dl[f] = sl[f]; }
        }

        const int nkb = 2 * qb + 2;
        issue_stage(0, 0);

        float acc[8][4] = {};
        float mo1 = -1e30f, mo2 = -1e30f, l1 = 0.0f, l2 = 0.0f;
        const int q1g = qb * 128 + wid * 16 + (lane >> 2);
        const int warp_qmax = qb * 128 + wid * 16 + 15;

        for (int kb = 0; kb < nkb; kb++) {
            const int s = kb & 1;
            if (kb + 1 < nkb) { issue_stage(s ^ 1, kb + 1); CP_WAIT1(); }
            else              { CP_WAIT0(); }
            __syncthreads();

            const bool tile_active = (kb * 64 <= warp_qmax);

            if (tile_active) {
                const uint32_t kb_ld = t_ld + s * ASTAGE;

                float sc[8][4] = {};
                #pragma unroll
                for (int ks = 0; ks < 4; ks++) {
                    uint32_t ah[4], al[4];
                    LDSM_X4(ah[0], ah[1], ah[2], ah[3], a_ld + ks * 32 + 0 * AQTILE);
                    LDSM_X4(al[0], al[1], al[2], al[3], a_ld + ks * 32 + 1 * AQTILE);
                    #pragma unroll
                    for (int nb = 0; nb < 4; nb++) {
                        if (kb * 64 + nb * 16 > warp_qmax) continue;
                        uint32_t r0, r1, r2, r3, q0, q1, q2, q3;
                        LDSM_X4(r0, r1, r2, r3, kb_ld + nb * 16 * AQP + ks * 32 + 0 * AKTILE);
                        LDSM_X4(q0, q1, q2, q3, kb_ld + nb * 16 * AQP + ks * 32 + 1 * AKTILE);
                        uint32_t be[2] = {r0, r2}, bo[2] = {r1, r3};
                        uint32_t le[2] = {q0, q2}, lo_[2] = {q1, q3};
                        MMA_BF16(sc[2 * nb],     ah, be); MMA_BF16(sc[2 * nb],     ah, le); MMA_BF16(sc[2 * nb],     al, be);
                        MMA_BF16(sc[2 * nb + 1], ah, bo); MMA_BF16(sc[2 * nb + 1], ah, lo_); MMA_BF16(sc[2 * nb + 1], al, bo);
                    }
                }

                if (kb * 64 + 63 > qb * 128 + wid * 16) {
                    #pragma unroll
                    for (int j = 0; j < 8; j++) {
                        const int c = kb * 64 + j * 8 + (lane & 3) * 2;
                        if (c     > q1g)     sc[j][0] = -1e30f;
                        if (c + 1 > q1g)     sc[j][1] = -1e30f;
                        if (c     > q1g + 8) sc[j][2] = -1e30f;
                        if (c + 1 > q1g + 8) sc[j][3] = -1e30f;
                    }
                }

                float m1 = -1e30f, m2 = -1e30f;
                #pragma unroll
                for (int j = 0; j < 8; j++) {
                    m1 = fmaxf(m1, fmaxf(sc[j][0], sc[j][1]));
                    m2 = fmaxf(m2, fmaxf(sc[j][2], sc[j][3]));
                }
                m1 = fmaxf(m1, __shfl_xor_sync(0xffffffffu, m1, 1));
                m1 = fmaxf(m1, __shfl_xor_sync(0xffffffffu, m1, 2));
                m2 = fmaxf(m2, __shfl_xor_sync(0xffffffffu, m2, 1));
                m2 = fmaxf(m2, __shfl_xor_sync(0xffffffffu, m2, 2));
                const float mn1 = fmaxf(mo1, m1), mn2 = fmaxf(mo2, m2);
                const float sc1 = __expf(mo1 - mn1), sc2 = __expf(mo2 - mn2);
                float sum1 = 0.0f, sum2 = 0.0f;
                #pragma unroll
                for (int j = 0; j < 8; j++) {
                    sc[j][0] = __expf(sc[j][0] - mn1); sum1 += sc[j][0];
                    sc[j][1] = __expf(sc[j][1] - mn1); sum1 += sc[j][1];
                    sc[j][2] = __expf(sc[j][2] - mn2); sum2 += sc[j][2];
                    sc[j][3] = __expf(sc[j][3] - mn2); sum2 += sc[j][3];
                }
                sum1 += __shfl_xor_sync(0xffffffffu, sum1, 1);
                sum1 += __shfl_xor_sync(0xffffffffu, sum1, 2);
                sum2 += __shfl_xor_sync(0xffffffffu, sum2, 1);
                sum2 += __shfl_xor_sync(0xffffffffu, sum2, 2);
                l1 = l1 * sc1 + sum1; l2 = l2 * sc2 + sum2;
                mo1 = mn1; mo2 = mn2;
                #pragma unroll
                for (int j = 0; j < 8; j++) {
                    acc[j][0] *= sc1; acc[j][1] *= sc1;
                    acc[j][2] *= sc2; acc[j][3] *= sc2;
                }

                #pragma unroll
                for (int ks = 0; ks < 4; ks++) {
                    if (kb * 64 + ks * 16 > warp_qmax) continue;
                    uint32_t ph[4], pl[4];
                    #pragma unroll
                    for (int t2 = 0; t2 < 2; t2++) {
                        const int j = 2 * ks + t2;
                        __nv_bfloat16 h0 = __float2bfloat16_rn(sc[j][0]);
                        __nv_bfloat16 h1 = __float2bfloat16_rn(sc[j][1]);
                        __nv_bfloat16 h2 = __float2bfloat16_rn(sc[j][2]);
                        __nv_bfloat16 h3 = __float2bfloat16_rn(sc[j][3]);
                        ph[2 * t2]     = pk_bf16x2(h0, h1);
                        ph[2 * t2 + 1] = pk_bf16x2(h2, h3);
                        pl[2 * t2]     = pk_bf16x2(
                            __float2bfloat16_rn(sc[j][0] - __bfloat162float(h0)),
                            __float2bfloat16_rn(sc[j][1] - __bfloat162float(h1)));
                        pl[2 * t2 + 1] = pk_bf16x2(
                            __float2bfloat16_rn(sc[j][2] - __bfloat162float(h2)),
                            __float2bfloat16_rn(sc[j][3] - __bfloat162float(h3)));
                    }
                    #pragma unroll
                    for (int nb = 0; nb < 4; nb++) {
                        uint32_t r0, r1, r2, r3, q0, q1, q2, q3;
                        LDSM_X4(r0, r1, r2, r3, kb_ld + nb * 16 * AQP + ks * 32 + 2 * AKTILE);
                        LDSM_X4(q0, q1, q2, q3, kb_ld + nb * 16 * AQP + ks * 32 + 3 * AKTILE);
                        uint32_t be[2] = {r0, r2}, bo[2] = {r1, r3};
                        uint32_t le[2] = {q0, q2}, lo_[2] = {q1, q3};
                        MMA_BF16(acc[2 * nb],     ph, be); MMA_BF16(acc[2 * nb],     ph, le); MMA_BF16(acc[2 * nb],     pl, be);
                        MMA_BF16(acc[2 * nb + 1], ph, bo); MMA_BF16(acc[2 * nb + 1], ph, lo_); MMA_BF16(acc[2 * nb + 1], pl, bo);
                    }
                }
            }
            __syncthreads();
        }

        /* epilogue: normalize, tf32-round, store fp32 */
        const float i1 = 1.0f / l1, i2 = 1.0f / l2;
        const size_t r1a = qkrow0 + (size_t)(qb * 128 + wid * 16 + (lane >> 2)) * D_MODEL;
        const size_t r2a = r1a + 8 * D_MODEL;
        #pragma unroll
        for (int j = 0; j < 8; j++) {
            const int c = j * 8 + (lane & 3) * 2;
            *(float2*)(o + r1a + c) = make_float2(tf32r(acc[j][0] * i1), tf32r(acc[j][1] * i1));
            *(float2*)(o + r2a + c) = make_float2(tf32r(acc[j][2] * i2), tf32r(acc[j][3] * i2));
        }
        __syncthreads();   /* all LDSM reads done before next qi overwrites Q */
    }
}

/* ============================================================ */
extern "C" void kernel_launch(void* const* d_in, const int* in_sizes, int n_in,
                              void* d_out, int out_size)
{
    const float* x  = (const float*)d_in[0];
    const float* W[4] = { (const float*)d_in[1], (const float*)d_in[2],
                          (const float*)d_in[3], (const float*)d_in[4] };
    float* out = (float*)d_out;

    float *qp, *kp, *vp, *xr, *wr;
    __nv_bfloat16 *qhp, *qlp, *khp, *klp, *vthp, *vtlp;
    cudaGetSymbolAddress((void**)&qp, g_q);
    cudaGetSymbolAddress((void**)&kp, g_k);
    cudaGetSymbolAddress((void**)&vp, g_v);
    cudaGetSymbolAddress((void**)&xr, g_xr);
    cudaGetSymbolAddress((void**)&wr, g_wr);
    cudaGetSymbolAddress((void**)&qhp, g_qh);
    cudaGetSymbolAddress((void**)&qlp, g_ql);
    cudaGetSymbolAddress((void**)&khp, g_kh);
    cudaGetSymbolAddress((void**)&klp, g_kl);
    cudaGetSymbolAddress((void**)&vthp, g_vth);
    cudaGetSymbolAddress((void**)&vtlp, g_vtl);

    static bool attr_done = false;
    if (!attr_done) {
        cudaFuncSetAttribute(gemm_tf32_kernel,
                             cudaFuncAttributeMaxDynamicSharedMemorySize, GEMM_SMEM);
        cudaFuncSetAttribute(attn_mma_kernel,
                             cudaFuncAttributeMaxDynamicSharedMemorySize, ATTN_SMEM);
        attr_done = true;
    }

    const size_t WSZ = (size_t)D_MODEL * D_MODEL;

    round_all_kernel<<<8192, 256>>>(x, W[0], W[1], W[2], W[3], xr, wr);

    const dim3 gg(D_MODEL / 128, M_TOT / 128);   /* (8, 32) */

    gemm_tf32_kernel<<<gg, 256, GEMM_SMEM>>>(xr, wr + 0 * WSZ, qp, M_TOT, D_MODEL, D_MODEL);
    gemm_tf32_kernel<<<gg, 256, GEMM_SMEM>>>(xr, wr + 1 * WSZ, kp, M_TOT, D_MODEL, D_MODEL);
    gemm_tf32_kernel<<<gg, 256, GEMM_SMEM>>>(xr, wr + 2 * WSZ, vp, M_TOT, D_MODEL, D_MODEL);

    rope2_kernel<<<M_TOT / 8, 256>>>(qp, kp, qhp, qlp, khp, klp);
    vtrans_kernel<<<dim3(SEQ / 64, BATCH * N_HEADS), 256>>>(vp, vthp, vtlp);

    /* paired q-blocks: grid.x = NQB/2 = 8 */
    attn_mma_kernel<<<dim3(NQB / 2, BATCH * N_HEADS), 256, ATTN_SMEM>>>(
        qhp, qlp, khp, klp, vthp, vtlp, qp);

    gemm_tf32_kernel<<<gg, 256, GEMM_SMEM>>>(qp, wr + 3 * WSZ, out, M_TOT, D_MODEL, D_MODEL);
}